// round 10
// baseline (speedup 1.0000x reference)
#include <cuda_runtime.h>
#include <cuda_bf16.h>
#include <cstdint>

// ---------------- constants ----------------
#define E_    192
#define DI_   384
#define NS_   16
#define NR_   12
#define L_    401
#define BATCH_ 32
#define NTOK_ (BATCH_*L_)     // 12832
#define XP_   48              // padded xdb row stride (44 used)
#define EPS_  1e-5f

// ---------------- scratch (static device globals; no allocation) ----------------
__device__ float g_x  [NTOK_*E_];        // hidden
__device__ float g_res[NTOK_*E_];        // residual
__device__ float g_xz [NTOK_*2*DI_];     // in_proj out (xm | z)
__device__ float g_xdb[NTOK_*XP_];       // x_proj out (dt_r | B | C), padded
__device__ float g_y  [NTOK_*DI_];       // scan output (gated)

// bf16 hi/lo packed operands for tensor-core GEMMs
__device__ __nv_bfloat16 g_a2 [(long)NTOK_*3*E_];     // in_proj A'  [M, 576]
__device__ __nv_bfloat16 g_a2o[(long)NTOK_*3*DI_];    // out_proj A' [M, 1152]
__device__ __nv_bfloat16 g_b2 [4ll*768*3*E_];         // in_proj  W' 4 layers
__device__ __nv_bfloat16 g_b2o[3ll*E_*3*DI_];         // out_proj W' 3 layers

// ---------------- warp-MMA helpers (compute_103-safe PTX) ----------------
__device__ __forceinline__ uint32_t smem_u32(const void* p) {
    uint32_t a;
    asm("{ .reg .u64 t; cvta.to.shared.u64 t, %1; cvt.u32.u64 %0, t; }"
        : "=r"(a) : "l"(p));
    return a;
}
__device__ __forceinline__ void ldsm4(uint32_t* r, uint32_t addr) {
    asm volatile("ldmatrix.sync.aligned.m8n8.x4.shared.b16 {%0,%1,%2,%3}, [%4];"
        : "=r"(r[0]), "=r"(r[1]), "=r"(r[2]), "=r"(r[3]) : "r"(addr));
}
__device__ __forceinline__ void mma_bf16(float* c, const uint32_t* a, const uint32_t* b) {
    asm volatile("mma.sync.aligned.m16n8k16.row.col.f32.bf16.bf16.f32 "
        "{%0,%1,%2,%3}, {%4,%5,%6,%7}, {%8,%9}, {%0,%1,%2,%3};"
        : "+f"(c[0]), "+f"(c[1]), "+f"(c[2]), "+f"(c[3])
        : "r"(a[0]), "r"(a[1]), "r"(a[2]), "r"(a[3]), "r"(b[0]), "r"(b[1]));
}
__device__ __forceinline__ void split3(float x, __nv_bfloat16* dst, long s, int bmode) {
    __nv_bfloat16 hi = __float2bfloat16(x);
    __nv_bfloat16 lo = __float2bfloat16(x - __bfloat162float(hi));
    dst[0] = hi;
    if (bmode) { dst[s] = hi; dst[2*s] = lo; }
    else       { dst[s] = lo; dst[2*s] = hi; }
}

// ---------------- patch embed + pos + cnn conv + cls ----------------
__global__ void k_embed(const float* __restrict__ imgs, const float* __restrict__ pw,
                        const float* __restrict__ pb,   const float* __restrict__ cls,
                        const float* __restrict__ pos,  const float* __restrict__ cw,
                        const float* __restrict__ cb)
{
    int idx = blockIdx.x*blockDim.x + threadIdx.x;
    if (idx >= NTOK_*E_) return;
    int e = idx % E_;
    int t = idx / E_;
    int l = t % L_;
    int b = t / L_;
    float v;
    if (l == L_-1) {
        v = cls[e] + pos[(L_-1)*E_ + e];
    } else {
        float acc = cb[e];
        const float* w4 = pw + e*4;
#pragma unroll
        for (int k = 0; k < 3; k++) {
            int ls = l - 1 + k;
            if (ls >= 0 && ls < 400) {
                const float* im = imgs + b*1600 + ls*4;
                float pe = im[0]*w4[0] + im[1]*w4[1] + im[2]*w4[2] + im[3]*w4[3]
                         + pb[e] + pos[ls*E_ + e];
                acc = fmaf(pe, cw[e*3 + k], acc);
            }
        }
        v = acc;
    }
    g_x[t*E_ + e] = v;
}

// ---------------- batched weight split (once per run) ----------------
__global__ void k_wcvt(const float* __restrict__ src, __nv_bfloat16* __restrict__ dst,
                       int Rd, int K, int Rs, long lsrc, long ldst)
{
    int idx = blockIdx.x*blockDim.x + threadIdx.x;
    if (idx >= Rd*K) return;
    int lay = blockIdx.y;
    int k = idx % K, r = idx / K;
    float x = (r < Rs) ? src[lay*lsrc + (long)r*K + k] : 0.f;
    split3(x, dst + lay*ldst + (long)r*3*K + k, K, 1);   // B side: [hi|hi|lo]
}

// ---------------- residual accumulate + rmsnorm + A-split ----------------
__global__ void k_resnorm(const float* __restrict__ norm_w, int first)
{
    int t = blockIdx.x;
    int e = threadIdx.x;     // 192 threads
    float r = g_x[t*E_ + e];
    if (!first) r += g_res[t*E_ + e];
    g_res[t*E_ + e] = r;
    float s = r*r;
#pragma unroll
    for (int o = 16; o > 0; o >>= 1) s += __shfl_down_sync(0xffffffffu, s, o);
    __shared__ float ws[6];
    __shared__ float s_inv;
    int w = e >> 5, lane = e & 31;
    if (lane == 0) ws[w] = s;
    __syncthreads();
    if (e == 0) {
        float tot = ws[0]+ws[1]+ws[2]+ws[3]+ws[4]+ws[5];
        s_inv = rsqrtf(tot * (1.0f/E_) + EPS_);
    }
    __syncthreads();
    float hn = r * s_inv * norm_w[e];
    split3(hn, g_a2 + (long)t*3*E_ + e, E_, 0);          // A side: [hi|lo|hi]
}

// ---------------- y -> bf16 hi/lo split (vectorized, layers 0-2) ----------------
__global__ void k_ycvt()
{
    int idx = blockIdx.x*blockDim.x + threadIdx.x;
    if (idx >= NTOK_*(DI_/4)) return;
    int r = idx / (DI_/4);
    int k4 = (idx % (DI_/4)) * 4;
    float4 v = *(const float4*)(g_y + (long)r*DI_ + k4);
    __nv_bfloat16 hi[4], lo[4];
    float vv[4] = {v.x, v.y, v.z, v.w};
#pragma unroll
    for (int i = 0; i < 4; i++) {
        hi[i] = __float2bfloat16(vv[i]);
        lo[i] = __float2bfloat16(vv[i] - __bfloat162float(hi[i]));
    }
    __nv_bfloat16* base = g_a2o + (long)r*3*DI_ + k4;
    *(uint2*)(base)         = *(uint2*)hi;
    *(uint2*)(base + DI_)   = *(uint2*)lo;
    *(uint2*)(base + 2*DI_) = *(uint2*)hi;
}

// =========================================================================
// HMMA bf16 GEMM: C[M,Nn] = A2[M,Keff] * B2[Nn,Keff]^T (fp32 accum)
// CTA tile 128 x BN, BK=32, double-buffered smem, warp tile 64x32.
// =========================================================================
template<int BN, int NTH>
__global__ __launch_bounds__(NTH)
void hgemm(const __nv_bfloat16* __restrict__ A2, const __nv_bfloat16* __restrict__ B2,
           float* __restrict__ C, int M, int Keff, int Nn, int ldc)
{
    constexpr int WN = BN/32;                 // warps along N
    constexpr int NLA = 512/NTH;              // A uint4 loads per thread
    constexpr int NLB = (BN*4)/NTH;           // B uint4 loads per thread
    constexpr int ASTRIDE = 40;               // bf16 elems per smem row
    __shared__ __align__(16) __nv_bfloat16 sA[2][128][ASTRIDE];
    __shared__ __align__(16) __nv_bfloat16 sB[2][BN][ASTRIDE];
    constexpr uint32_t ABUF = 128*ASTRIDE*2;  // bytes per A buffer
    constexpr uint32_t BBUF = BN*ASTRIDE*2;

    int tid = threadIdx.x, wid = tid >> 5, lane = tid & 31;
    int wm = wid / WN, wn = wid % WN;
    int m0 = blockIdx.y * 128;
    int n0 = blockIdx.x * BN;

    uint32_t a_addr[4], b_addr[2];
#pragma unroll
    for (int am = 0; am < 4; am++) {
        int row = wm*64 + am*16 + (lane & 15);
        int colb = (lane >> 4) * 16;
        a_addr[am] = smem_u32(&sA[0][row][0]) + colb;
    }
#pragma unroll
    for (int p = 0; p < 2; p++) {
        int row = wn*32 + p*16 + (lane & 7) + ((lane >> 4) << 3);
        int colb = ((lane >> 3) & 1) * 16;
        b_addr[p] = smem_u32(&sB[0][row][0]) + colb;
    }

    float c[4][4][4];
#pragma unroll
    for (int i = 0; i < 4; i++)
#pragma unroll
        for (int j = 0; j < 4; j++)
#pragma unroll
            for (int k = 0; k < 4; k++) c[i][j][k] = 0.f;

    uint4 ra[NLA], rb[NLB];

#define H_LDG(k0)                                                             \
    {                                                                         \
        _Pragma("unroll")                                                     \
        for (int i = 0; i < NLA; i++) {                                       \
            int g = tid + i*NTH;                                              \
            int row = g >> 2, seg = g & 3;                                    \
            ra[i] = (m0 + row < M)                                            \
                ? *(const uint4*)(A2 + (long)(m0+row)*Keff + (k0) + seg*8)    \
                : make_uint4(0u,0u,0u,0u);                                    \
        }                                                                     \
        _Pragma("unroll")                                                     \
        for (int i = 0; i < NLB; i++) {                                       \
            int g = tid + i*NTH;                                              \
            int row = g >> 2, seg = g & 3;                                    \
            rb[i] = *(const uint4*)(B2 + (long)(n0+row)*Keff + (k0) + seg*8); \
        }                                                                     \
    }
#define H_STS(buf)                                                            \
    {                                                                         \
        _Pragma("unroll")                                                     \
        for (int i = 0; i < NLA; i++) {                                       \
            int g = tid + i*NTH;                                              \
            int row = g >> 2, seg = g & 3;                                    \
            *(uint4*)&sA[buf][row][seg*8] = ra[i];                            \
        }                                                                     \
        _Pragma("unroll")                                                     \
        for (int i = 0; i < NLB; i++) {                                       \
            int g = tid + i*NTH;                                              \
            int row = g >> 2, seg = g & 3;                                    \
            *(uint4*)&sB[buf][row][seg*8] = rb[i];                            \
        }                                                                     \
    }
#define H_COMP(buf)                                                           \
    {                                                                         \
        uint32_t aoff = (buf)*ABUF, boff = (buf)*BBUF;                        \
        _Pragma("unroll")                                                     \
        for (int ks = 0; ks < 2; ks++) {                                      \
            uint32_t af[4][4], bf[2][4];                                      \
            _Pragma("unroll")                                                 \
            for (int am = 0; am < 4; am++)                                    \
                ldsm4(af[am], a_addr[am] + aoff + ks*32);                     \
            _Pragma("unroll")                                                 \
            for (int p = 0; p < 2; p++)                                       \
                ldsm4(bf[p], b_addr[p] + boff + ks*32);                       \
            _Pragma("unroll")                                                 \
            for (int am = 0; am < 4; am++)                                    \
                _Pragma("unroll")                                             \
                for (int bn = 0; bn < 4; bn++)                                \
                    mma_bf16(c[am][bn], af[am], &bf[bn>>1][(bn&1)*2]);        \
        }                                                                     \
    }

    int nchunk = Keff >> 5;
    H_LDG(0);
    H_STS(0);
    __syncthreads();
    for (int ck = 0; ck < nchunk; ck++) {
        if (ck + 1 < nchunk) H_LDG((ck+1)*32);
        H_COMP(ck & 1);
        if (ck + 1 < nchunk) {
            H_STS((ck+1) & 1);
        }
        __syncthreads();
    }

    // epilogue: direct fp32 stores
#pragma unroll
    for (int am = 0; am < 4; am++) {
        int r0 = m0 + wm*64 + am*16 + (lane >> 2);
        int r1 = r0 + 8;
#pragma unroll
        for (int bn = 0; bn < 4; bn++) {
            int col = n0 + wn*32 + bn*8 + (lane & 3)*2;
            if (col < Nn) {
                if (r0 < M) *(float2*)(C + (long)r0*ldc + col) = make_float2(c[am][bn][0], c[am][bn][1]);
                if (r1 < M) *(float2*)(C + (long)r1*ldc + col) = make_float2(c[am][bn][2], c[am][bn][3]);
            }
        }
    }
#undef H_LDG
#undef H_STS
#undef H_COMP
}

// =========================================================================
// x_proj SGEMM with FUSED depthwise conv+silu on the A side (fp32):
// A[t, d] = silu(sum_j xz[t-3+j, d] * cw[d,j] + cb[d])   (causal, in-batch)
// C[M,48(44 used)] = A[M,384] * B[44,384]^T.  64x48 tile, 256 threads.
// =========================================================================
__global__ __launch_bounds__(256)
void k_xp(const float* __restrict__ Bm, const float* __restrict__ cwp,
          const float* __restrict__ cbp, float* __restrict__ C, int M)
{
    __shared__ float As[2][16][64];
    __shared__ float Bs[2][16][48];
    int tid = threadIdx.x;
    int m0 = blockIdx.x * 64;
    int tm = tid >> 4;          // 0..15 -> 4 rows each
    int tn = tid & 15;          // 0..15 -> 3 cols each
    int lrow = tid >> 2;        // 0..63
    int lkq  = tid & 3;         // 0..3

    int tok = m0 + lrow;
    bool mv = tok < M;
    int lpos = tok % L_;

    float acc[4][3];
#pragma unroll
    for (int i = 0; i < 4; i++)
#pragma unroll
        for (int j = 0; j < 3; j++) acc[i][j] = 0.f;

    float4 xs[4], wv[4], cb4, rb;
#define ALDG(k0)                                                              \
    {                                                                         \
        int ch = (k0) + lkq*4;                                                \
        float4 z4 = make_float4(0.f,0.f,0.f,0.f);                             \
        cb4 = mv ? *(const float4*)(cbp + ch) : z4;                           \
        _Pragma("unroll")                                                     \
        for (int j = 0; j < 4; j++)                                           \
            xs[j] = (mv && (lpos-3+j) >= 0)                                   \
                ? *(const float4*)(g_xz + (long)(tok-3+j)*(2*DI_) + ch)       \
                : z4;                                                         \
        _Pragma("unroll")                                                     \
        for (int i = 0; i < 4; i++)                                           \
            wv[i] = mv ? *(const float4*)(cwp + (ch+i)*4) : z4;               \
        rb = z4;                                                              \
        if (tid < 192 && lrow < 44)                                           \
            rb = *(const float4*)(Bm + (long)lrow*DI_ + (k0) + lkq*4);        \
    }
#define ASTS(buf)                                                             \
    {                                                                         \
        float av[4];                                                          \
        float xj[4][4];                                                       \
        *(float4*)xj[0] = xs[0]; *(float4*)xj[1] = xs[1];                     \
        *(float4*)xj[2] = xs[2]; *(float4*)xj[3] = xs[3];                     \
        float wb[4][4];                                                       \
        *(float4*)wb[0] = wv[0]; *(float4*)wb[1] = wv[1];                     \
        *(float4*)wb[2] = wv[2]; *(float4*)wb[3] = wv[3];                     \
        float cbv[4]; *(float4*)cbv = cb4;                                    \
        _Pragma("unroll")                                                     \
        for (int i = 0; i < 4; i++) {                                         \
            float t0 = cbv[i];                                                \
            t0 = fmaf(wb[i][0], xj[0][i], t0);                                \
            t0 = fmaf(wb[i][1], xj[1][i], t0);                                \
            t0 = fmaf(wb[i][2], xj[2][i], t0);                                \
            t0 = fmaf(wb[i][3], xj[3][i], t0);                                \
            av[i] = t0 / (1.f + __expf(-t0));                                 \
        }                                                                     \
        As[buf][lkq*4+0][lrow] = av[0]; As[buf][lkq*4+1][lrow] = av[1];       \
        As[buf][lkq*4+2][lrow] = av[2]; As[buf][lkq*4+3][lrow] = av[3];       \
        if (tid < 192) {                                                      \
            Bs[buf][lkq*4+0][lrow] = rb.x; Bs[buf][lkq*4+1][lrow] = rb.y;     \
            Bs[buf][lkq*4+2][lrow] = rb.z; Bs[buf][lkq*4+3][lrow] = rb.w;     \
        }                                                                     \
    }
#define ACOMP(buf)                                                            \
    {                                                                         \
        _Pragma("unroll")                                                     \
        for (int kk = 0; kk < 16; kk++) {                                     \
            float a4[4];                                                      \
            *(float4*)a4 = *(const float4*)&As[buf][kk][tm*4];                \
            float b0 = Bs[buf][kk][tn*3+0];                                   \
            float b1 = Bs[buf][kk][tn*3+1];                                   \
            float b2 = Bs[buf][kk][tn*3+2];                                   \
            _Pragma("unroll")                                                 \
            for (int i = 0; i < 4; i++) {                                     \
                acc[i][0] = fmaf(a4[i], b0, acc[i][0]);                       \
                acc[i][1] = fmaf(a4[i], b1, acc[i][1]);                       \
                acc[i][2] = fmaf(a4[i], b2, acc[i][2]);                       \
            }                                                                 \
        }                                                                     \
    }

    ALDG(0); ASTS(0);
    __syncthreads();
    int buf = 0;
    for (int k0 = 16; k0 < DI_; k0 += 16) {
        ALDG(k0);
        ACOMP(buf);
        ASTS(buf ^ 1);
        __syncthreads();
        buf ^= 1;
    }
    ACOMP(buf);

#pragma unroll
    for (int i = 0; i < 4; i++) {
        int row = m0 + tm*4 + i;
        if (row < M) {
#pragma unroll
            for (int j = 0; j < 3; j++)
                C[(long)row*XP_ + tn*3 + j] = acc[i][j];
        }
    }
#undef ALDG
#undef ASTS
#undef ACOMP
}

// =========================================================================
// Fused selective scan: rolling depthwise conv + dt(softplus) + SSM + gate.
// 4 threads per (b,d) channel; grid (12, 32), block 128.
// =========================================================================
__global__ __launch_bounds__(128)
void k_scan(const float* __restrict__ A_log, const float* __restrict__ Dsk,
            const float* __restrict__ dtw_g, const float* __restrict__ dtb_g,
            const float* __restrict__ cwp,  const float* __restrict__ cbp)
{
    int local = blockIdx.x*128 + threadIdx.x;   // 0..1535
    int d = local >> 2;                          // 0..383
    int q = local & 3;                           // quarter of states
    int b = blockIdx.y;

    float a[4];
#pragma unroll
    for (int n = 0; n < 4; n++) a[n] = -__expf(A_log[d*NS_ + q*4 + n]);
    float w[NR_];
#pragma unroll
    for (int r = 0; r < NR_; r++) w[r] = dtw_g[d*NR_ + r];
    float dtb = dtb_g[d];
    float dsk = Dsk[d];
    float c0 = cwp[d*4+0], c1 = cwp[d*4+1], c2 = cwp[d*4+2], c3 = cwp[d*4+3];
    float cbv = cbp[d];
    float h[4] = {0.f, 0.f, 0.f, 0.f};

    long tbase = (long)b * L_;
    const float4* xr = (const float4*)(g_xdb + tbase*XP_);
    float4 r0 = xr[0], r1 = xr[1], r2 = xr[2];
    float4 Bq = xr[3+q], Cq = xr[7+q];
    float xm3 = 0.f, xm2 = 0.f, xm1 = 0.f;
    float xm0 = g_xz[tbase*(2*DI_) + d];
    float z   = g_xz[tbase*(2*DI_) + DI_ + d];

    for (int l = 0; l < L_; l++) {
        long t = tbase + l;
        long t2 = tbase + ((l+1 < L_) ? l+1 : l);
        const float4* x2 = (const float4*)(g_xdb + t2*XP_);
        float4 p0 = x2[0], p1 = x2[1], p2 = x2[2];
        float4 pB = x2[3+q], pC = x2[7+q];
        float pxm = g_xz[t2*(2*DI_) + d];
        float pz  = g_xz[t2*(2*DI_) + DI_ + d];

        // depthwise conv(4) + silu (rolling window)
        float cacc = fmaf(c3, xm0, fmaf(c2, xm1, fmaf(c1, xm2, fmaf(c0, xm3, cbv))));
        float u = cacc / (1.f + __expf(-cacc));

        // dt = softplus(dot12 + bias)
        float a0 = dtb, a1 = 0.f;
        a0 = fmaf(r0.x, w[0], a0); a1 = fmaf(r0.y, w[1],  a1);
        a0 = fmaf(r0.z, w[2], a0); a1 = fmaf(r0.w, w[3],  a1);
        a0 = fmaf(r1.x, w[4], a0); a1 = fmaf(r1.y, w[5],  a1);
        a0 = fmaf(r1.z, w[6], a0); a1 = fmaf(r1.w, w[7],  a1);
        a0 = fmaf(r2.x, w[8], a0); a1 = fmaf(r2.y, w[9],  a1);
        a0 = fmaf(r2.z, w[10],a0); a1 = fmaf(r2.w, w[11], a1);
        float acc = a0 + a1;
        float dt = fmaxf(acc, 0.f) + __logf(1.f + __expf(-fabsf(acc)));
        float du = dt * u;

        float Bv[4] = {Bq.x, Bq.y, Bq.z, Bq.w};
        float Cv[4] = {Cq.x, Cq.y, Cq.z, Cq.w};
        float y = 0.f;
#pragma unroll
        for (int n = 0; n < 4; n++) {
            float dA = __expf(dt * a[n]);
            h[n] = fmaf(h[n], dA, du * Bv[n]);
            y = fmaf(h[n], Cv[n], y);
        }
        y += __shfl_xor_sync(0xffffffffu, y, 1);
        y += __shfl_xor_sync(0xffffffffu, y, 2);
        if (q == 0) {
            float sg = z / (1.f + __expf(-z));
            g_y[t*DI_ + d] = (y + u*dsk) * sg;
        }
        r0 = p0; r1 = p1; r2 = p2; Bq = pB; Cq = pC;
        xm3 = xm2; xm2 = xm1; xm1 = xm0; xm0 = pxm; z = pz;
    }
}

// ---------------- layer-3 out_proj: only last tokens matter ----------------
__global__ void k_outlast(const float* __restrict__ ow)
{
    int b = blockIdx.x;
    int e = threadIdx.x;         // 192
    __shared__ float ys[DI_];
    int t = b*L_ + (L_-1);
    for (int i = e; i < DI_; i += E_) ys[i] = g_y[(long)t*DI_ + i];
    __syncthreads();
    float acc = 0.f;
    const float* w = ow + e*DI_;
#pragma unroll 4
    for (int d2 = 0; d2 < DI_; d2++) acc = fmaf(ys[d2], w[d2], acc);
    g_x[t*E_ + e] = acc;
}

// ---------------- final rmsnorm (last token) + classifier head ----------------
__global__ void k_final(const float* __restrict__ nfw, const float* __restrict__ hw,
                        const float* __restrict__ hb, float* __restrict__ out)
{
    int b = blockIdx.x;
    int e = threadIdx.x;         // 192
    int t = b*L_ + (L_-1);
    float r = g_x[t*E_ + e] + g_res[t*E_ + e];
    float s = r*r;
#pragma unroll
    for (int o = 16; o > 0; o >>= 1) s += __shfl_down_sync(0xffffffffu, s, o);
    __shared__ float ws[6];
    __shared__ float s_inv;
    __shared__ float vs[E_];
    int w = e >> 5, lane = e & 31;
    if (lane == 0) ws[w] = s;
    __syncthreads();
    if (e == 0) {
        float tot = ws[0]+ws[1]+ws[2]+ws[3]+ws[4]+ws[5];
        s_inv = rsqrtf(tot * (1.0f/E_) + EPS_);
    }
    __syncthreads();
    vs[e] = r * s_inv * nfw[e];
    __syncthreads();
    if (e < 20) {
        float acc = hb[e];
        const float* wr = hw + e*E_;
#pragma unroll 4
        for (int j = 0; j < E_; j++) acc = fmaf(vs[j], wr[j], acc);
        out[b*20 + e] = acc;
    }
}

// ---------------- launch ----------------
extern "C" void kernel_launch(void* const* d_in, const int* in_sizes, int n_in,
                              void* d_out, int out_size)
{
    const float* imgs      = (const float*)d_in[0];
    const float* patch_w   = (const float*)d_in[1];
    const float* patch_b   = (const float*)d_in[2];
    const float* cls_token = (const float*)d_in[3];
    const float* pos_embed = (const float*)d_in[4];
    const float* cnn_w     = (const float*)d_in[5];
    const float* cnn_b     = (const float*)d_in[6];
    const float* norm_w    = (const float*)d_in[7];
    const float* in_proj_w = (const float*)d_in[8];
    const float* conv_w    = (const float*)d_in[9];
    const float* conv_b    = (const float*)d_in[10];
    const float* x_proj_w  = (const float*)d_in[11];
    const float* dt_proj_w = (const float*)d_in[12];
    const float* dt_proj_b = (const float*)d_in[13];
    const float* A_log     = (const float*)d_in[14];
    const float* D_skip    = (const float*)d_in[15];
    const float* out_proj_w= (const float*)d_in[16];
    const float* norm_f_w  = (const float*)d_in[17];
    const float* head_w    = (const float*)d_in[18];
    const float* head_b    = (const float*)d_in[19];
    float* out = (float*)d_out;

    float *p_xz, *p_xdb, *p_y, *p_x;
    __nv_bfloat16 *p_a2, *p_a2o, *p_b2, *p_b2o;
    cudaGetSymbolAddress((void**)&p_xz,  g_xz);
    cudaGetSymbolAddress((void**)&p_xdb, g_xdb);
    cudaGetSymbolAddress((void**)&p_y,   g_y);
    cudaGetSymbolAddress((void**)&p_x,   g_x);
    cudaGetSymbolAddress((void**)&p_a2,  g_a2);
    cudaGetSymbolAddress((void**)&p_a2o, g_a2o);
    cudaGetSymbolAddress((void**)&p_b2,  g_b2);
    cudaGetSymbolAddress((void**)&p_b2o, g_b2o);

    // 1: embed
    k_embed<<<(NTOK_*E_ + 255)/256, 256>>>(imgs, patch_w, patch_b, cls_token,
                                           pos_embed, cnn_w, cnn_b);
    // 2-3: batched weight splits (all layers at once)
    k_wcvt<<<dim3((768*E_+255)/256, 4), 256>>>(in_proj_w, p_b2, 768, E_, 768,
                                               (long)768*E_, (long)768*3*E_);
    k_wcvt<<<dim3((E_*DI_+255)/256, 3), 256>>>(out_proj_w, p_b2o, E_, DI_, E_,
                                               (long)E_*DI_, (long)E_*3*DI_);

    const int MGRID = (NTOK_ + 127) / 128;   // 101
    dim3 gIn (6, MGRID);    // N tiles of 128 over 768
    dim3 gOut(3, MGRID);    // N tiles of 64 over 192
    int xp_blocks = (NTOK_ + 63) / 64;       // 201
    int yc_blocks = (NTOK_*(DI_/4) + 255)/256;

    for (int i = 0; i < 4; i++) {
        k_resnorm<<<NTOK_, E_>>>(norm_w + i*E_, i == 0);
        hgemm<128,256><<<gIn, 256>>>(p_a2, p_b2 + (long)i*768*3*E_, p_xz,
                                     NTOK_, 3*E_, 2*DI_, 2*DI_);
        k_xp<<<xp_blocks, 256>>>(x_proj_w + (long)i*(NR_+2*NS_)*DI_,
                                 conv_w + (long)i*DI_*4, conv_b + i*DI_,
                                 p_xdb, NTOK_);
        k_scan<<<dim3(12, BATCH_), 128>>>(A_log + (long)i*DI_*NS_, D_skip + i*DI_,
                                          dt_proj_w + (long)i*DI_*NR_,
                                          dt_proj_b + i*DI_,
                                          conv_w + (long)i*DI_*4, conv_b + i*DI_);
        if (i < 3) {
            k_ycvt<<<yc_blocks, 256>>>();
            hgemm<64,128><<<gOut, 128>>>(p_a2o, p_b2o + (long)i*E_*3*DI_, p_x,
                                         NTOK_, 3*DI_, E_, E_);
        } else {
            k_outlast<<<BATCH_, E_>>>(out_proj_w + (long)i*E_*DI_);
        }
    }
    k_final<<<BATCH_, E_>>>(norm_f_w, head_w, head_b, out);
}

// round 12
// speedup vs baseline: 1.0420x; 1.0420x over previous
#include <cuda_runtime.h>
#include <cuda_bf16.h>
#include <cstdint>

// ---------------- constants ----------------
#define E_    192
#define DI_   384
#define NS_   16
#define NR_   12
#define L_    401
#define BATCH_ 32
#define NTOK_ (BATCH_*L_)     // 12832
#define XP_   48              // padded xdb row stride (44 used)
#define EPS_  1e-5f

// ---------------- scratch (static device globals; no allocation) ----------------
__device__ float g_x  [NTOK_*E_];        // hidden
__device__ float g_res[NTOK_*E_];        // residual
__device__ float g_hn [NTOK_*E_];        // rmsnorm output (f32)
__device__ float g_xz [NTOK_*2*DI_];     // in_proj out (xm | z)
__device__ float g_xc [NTOK_*DI_];       // conv+silu out
__device__ float g_xdb[NTOK_*XP_];       // x_proj out (dt_r | B | C), padded
__device__ float g_y  [NTOK_*DI_];       // scan output (gated)

// bf16 hi/lo packed operands for tensor-core GEMMs
__device__ __nv_bfloat16 g_a2 [(long)NTOK_*3*E_];     // in_proj A'  [M, 576]
__device__ __nv_bfloat16 g_a2o[(long)NTOK_*3*DI_];    // out_proj A' [M, 1152]
__device__ __nv_bfloat16 g_b2 [4ll*768*3*E_];         // in_proj  W' 4 layers
__device__ __nv_bfloat16 g_b2o[3ll*E_*3*DI_];         // out_proj W' 3 layers

// ---------------- warp-MMA helpers (compute_103-safe PTX) ----------------
__device__ __forceinline__ uint32_t smem_u32(const void* p) {
    uint32_t a;
    asm("{ .reg .u64 t; cvta.to.shared.u64 t, %1; cvt.u32.u64 %0, t; }"
        : "=r"(a) : "l"(p));
    return a;
}
__device__ __forceinline__ void ldsm4(uint32_t* r, uint32_t addr) {
    asm volatile("ldmatrix.sync.aligned.m8n8.x4.shared.b16 {%0,%1,%2,%3}, [%4];"
        : "=r"(r[0]), "=r"(r[1]), "=r"(r[2]), "=r"(r[3]) : "r"(addr));
}
__device__ __forceinline__ void mma_bf16(float* c, const uint32_t* a, const uint32_t* b) {
    asm volatile("mma.sync.aligned.m16n8k16.row.col.f32.bf16.bf16.f32 "
        "{%0,%1,%2,%3}, {%4,%5,%6,%7}, {%8,%9}, {%0,%1,%2,%3};"
        : "+f"(c[0]), "+f"(c[1]), "+f"(c[2]), "+f"(c[3])
        : "r"(a[0]), "r"(a[1]), "r"(a[2]), "r"(a[3]), "r"(b[0]), "r"(b[1]));
}

// ---------------- patch embed + pos + cnn conv + cls ----------------
__global__ void k_embed(const float* __restrict__ imgs, const float* __restrict__ pw,
                        const float* __restrict__ pb,   const float* __restrict__ cls,
                        const float* __restrict__ pos,  const float* __restrict__ cw,
                        const float* __restrict__ cb)
{
    int idx = blockIdx.x*blockDim.x + threadIdx.x;
    if (idx >= NTOK_*E_) return;
    int e = idx % E_;
    int t = idx / E_;
    int l = t % L_;
    int b = t / L_;
    float v;
    if (l == L_-1) {
        v = cls[e] + pos[(L_-1)*E_ + e];
    } else {
        float acc = cb[e];
        const float* w4 = pw + e*4;
#pragma unroll
        for (int k = 0; k < 3; k++) {
            int ls = l - 1 + k;
            if (ls >= 0 && ls < 400) {
                const float* im = imgs + b*1600 + ls*4;
                float pe = im[0]*w4[0] + im[1]*w4[1] + im[2]*w4[2] + im[3]*w4[3]
                         + pb[e] + pos[ls*E_ + e];
                acc = fmaf(pe, cw[e*3 + k], acc);
            }
        }
        v = acc;
    }
    g_x[t*E_ + e] = v;
}

// ---------------- batched, vectorized weight split (B side: hi|hi|lo) ----------------
__global__ void k_wcvt(const float* __restrict__ src, __nv_bfloat16* __restrict__ dst,
                       int R, int K, long lsrc, long ldst)
{
    int idx = blockIdx.x*blockDim.x + threadIdx.x;
    int nk4 = K >> 2;
    if (idx >= R*nk4) return;
    int lay = blockIdx.y;
    int r = idx / nk4, k4 = (idx % nk4) << 2;
    float4 v = *(const float4*)(src + lay*lsrc + (long)r*K + k4);
    float vv[4] = {v.x, v.y, v.z, v.w};
    __nv_bfloat16 hi[4], lo[4];
#pragma unroll
    for (int i = 0; i < 4; i++) {
        hi[i] = __float2bfloat16(vv[i]);
        lo[i] = __float2bfloat16(vv[i] - __bfloat162float(hi[i]));
    }
    __nv_bfloat16* base = dst + lay*ldst + (long)r*3*K + k4;
    *(uint2*)(base)       = *(uint2*)hi;
    *(uint2*)(base + K)   = *(uint2*)hi;
    *(uint2*)(base + 2*K) = *(uint2*)lo;
}

// ---------------- vectorized activation split (A side: hi|lo|hi) ----------------
__global__ void k_acvt(const float* __restrict__ src, __nv_bfloat16* __restrict__ dst,
                       int R, int K)
{
    int idx = blockIdx.x*blockDim.x + threadIdx.x;
    int nk4 = K >> 2;
    if (idx >= R*nk4) return;
    int r = idx / nk4, k4 = (idx % nk4) << 2;
    float4 v = *(const float4*)(src + (long)r*K + k4);
    float vv[4] = {v.x, v.y, v.z, v.w};
    __nv_bfloat16 hi[4], lo[4];
#pragma unroll
    for (int i = 0; i < 4; i++) {
        hi[i] = __float2bfloat16(vv[i]);
        lo[i] = __float2bfloat16(vv[i] - __bfloat162float(hi[i]));
    }
    __nv_bfloat16* base = dst + (long)r*3*K + k4;
    *(uint2*)(base)       = *(uint2*)hi;
    *(uint2*)(base + K)   = *(uint2*)lo;
    *(uint2*)(base + 2*K) = *(uint2*)hi;
}

// ---------------- residual accumulate + rmsnorm (2 tokens per block) ----------------
__global__ __launch_bounds__(384)
void k_resnorm(const float* __restrict__ norm_w, int first)
{
    int grp = threadIdx.x / 192;     // 0..1
    int e   = threadIdx.x % 192;
    int t = blockIdx.x*2 + grp;      // NTOK_ even -> always valid
    float r = g_x[t*E_ + e];
    if (!first) r += g_res[t*E_ + e];
    g_res[t*E_ + e] = r;
    float s = r*r;
#pragma unroll
    for (int o = 16; o > 0; o >>= 1) s += __shfl_down_sync(0xffffffffu, s, o);
    __shared__ float ws[12];
    __shared__ float s_inv[2];
    int w = threadIdx.x >> 5, lane = threadIdx.x & 31;
    if (lane == 0) ws[w] = s;
    __syncthreads();
    if (e == 0) {
        int b0 = grp*6;
        float tot = ws[b0]+ws[b0+1]+ws[b0+2]+ws[b0+3]+ws[b0+4]+ws[b0+5];
        s_inv[grp] = rsqrtf(tot * (1.0f/E_) + EPS_);
    }
    __syncthreads();
    g_hn[t*E_ + e] = r * s_inv[grp] * norm_w[e];
}

// =========================================================================
// HMMA bf16 GEMM: C[M,Nn] = A2[M,Keff] * B2[Nn,Keff]^T (fp32 accum)
// CTA tile 128 x BN, BK=32, double-buffered smem, warp tile 64x32.
// =========================================================================
template<int BN, int NTH>
__global__ __launch_bounds__(NTH)
void hgemm(const __nv_bfloat16* __restrict__ A2, const __nv_bfloat16* __restrict__ B2,
           float* __restrict__ C, int M, int Keff, int Nn, int ldc)
{
    constexpr int WN = BN/32;                 // warps along N
    constexpr int NLA = 512/NTH;              // A uint4 loads per thread
    constexpr int NLB = (BN*4)/NTH;           // B uint4 loads per thread
    constexpr int ASTRIDE = 40;               // bf16 elems per smem row
    __shared__ __align__(16) __nv_bfloat16 sA[2][128][ASTRIDE];
    __shared__ __align__(16) __nv_bfloat16 sB[2][BN][ASTRIDE];
    constexpr uint32_t ABUF = 128*ASTRIDE*2;  // bytes per A buffer
    constexpr uint32_t BBUF = BN*ASTRIDE*2;

    int tid = threadIdx.x, wid = tid >> 5, lane = tid & 31;
    int wm = wid / WN, wn = wid % WN;
    int m0 = blockIdx.y * 128;
    int n0 = blockIdx.x * BN;

    uint32_t a_addr[4], b_addr[2];
#pragma unroll
    for (int am = 0; am < 4; am++) {
        int row = wm*64 + am*16 + (lane & 15);
        int colb = (lane >> 4) * 16;
        a_addr[am] = smem_u32(&sA[0][row][0]) + colb;
    }
#pragma unroll
    for (int p = 0; p < 2; p++) {
        int row = wn*32 + p*16 + (lane & 7) + ((lane >> 4) << 3);
        int colb = ((lane >> 3) & 1) * 16;
        b_addr[p] = smem_u32(&sB[0][row][0]) + colb;
    }

    float c[4][4][4];
#pragma unroll
    for (int i = 0; i < 4; i++)
#pragma unroll
        for (int j = 0; j < 4; j++)
#pragma unroll
            for (int k = 0; k < 4; k++) c[i][j][k] = 0.f;

    uint4 ra[NLA], rb[NLB];

#define H_LDG(k0)                                                             \
    {                                                                         \
        _Pragma("unroll")                                                     \
        for (int i = 0; i < NLA; i++) {                                       \
            int g = tid + i*NTH;                                              \
            int row = g >> 2, seg = g & 3;                                    \
            ra[i] = (m0 + row < M)                                            \
                ? *(const uint4*)(A2 + (long)(m0+row)*Keff + (k0) + seg*8)    \
                : make_uint4(0u,0u,0u,0u);                                    \
        }                                                                     \
        _Pragma("unroll")                                                     \
        for (int i = 0; i < NLB; i++) {                                       \
            int g = tid + i*NTH;                                              \
            int row = g >> 2, seg = g & 3;                                    \
            rb[i] = *(const uint4*)(B2 + (long)(n0+row)*Keff + (k0) + seg*8); \
        }                                                                     \
    }
#define H_STS(buf)                                                            \
    {                                                                         \
        _Pragma("unroll")                                                     \
        for (int i = 0; i < NLA; i++) {                                       \
            int g = tid + i*NTH;                                              \
            int row = g >> 2, seg = g & 3;                                    \
            *(uint4*)&sA[buf][row][seg*8] = ra[i];                            \
        }                                                                     \
        _Pragma("unroll")                                                     \
        for (int i = 0; i < NLB; i++) {                                       \
            int g = tid + i*NTH;                                              \
            int row = g >> 2, seg = g & 3;                                    \
            *(uint4*)&sB[buf][row][seg*8] = rb[i];                            \
        }                                                                     \
    }
#define H_COMP(buf)                                                           \
    {                                                                         \
        uint32_t aoff = (buf)*ABUF, boff = (buf)*BBUF;                        \
        _Pragma("unroll")                                                     \
        for (int ks = 0; ks < 2; ks++) {                                      \
            uint32_t af[4][4], bf[2][4];                                      \
            _Pragma("unroll")                                                 \
            for (int am = 0; am < 4; am++)                                    \
                ldsm4(af[am], a_addr[am] + aoff + ks*32);                     \
            _Pragma("unroll")                                                 \
            for (int p = 0; p < 2; p++)                                       \
                ldsm4(bf[p], b_addr[p] + boff + ks*32);                       \
            _Pragma("unroll")                                                 \
            for (int am = 0; am < 4; am++)                                    \
                _Pragma("unroll")                                             \
                for (int bn = 0; bn < 4; bn++)                                \
                    mma_bf16(c[am][bn], af[am], &bf[bn>>1][(bn&1)*2]);        \
        }                                                                     \
    }

    int nchunk = Keff >> 5;
    H_LDG(0);
    H_STS(0);
    __syncthreads();
    for (int ck = 0; ck < nchunk; ck++) {
        if (ck + 1 < nchunk) H_LDG((ck+1)*32);
        H_COMP(ck & 1);
        if (ck + 1 < nchunk) {
            H_STS((ck+1) & 1);
        }
        __syncthreads();
    }

    // epilogue: direct fp32 stores
#pragma unroll
    for (int am = 0; am < 4; am++) {
        int r0 = m0 + wm*64 + am*16 + (lane >> 2);
        int r1 = r0 + 8;
#pragma unroll
        for (int bn = 0; bn < 4; bn++) {
            int col = n0 + wn*32 + bn*8 + (lane & 3)*2;
            if (col < Nn) {
                if (r0 < M) *(float2*)(C + (long)r0*ldc + col) = make_float2(c[am][bn][0], c[am][bn][1]);
                if (r1 < M) *(float2*)(C + (long)r1*ldc + col) = make_float2(c[am][bn][2], c[am][bn][3]);
            }
        }
    }
#undef H_LDG
#undef H_STS
#undef H_COMP
}

// =========================================================================
// x_proj SGEMM (fp32): C[M,48(44 used)] = A[M,384] * B[44,384]^T
// 64x48 tile, 256 threads, double-buffered. 201 CTAs.
// =========================================================================
__global__ __launch_bounds__(256)
void sgemm_xp(const float* __restrict__ A, const float* __restrict__ Bm,
              float* __restrict__ C, int M)
{
    __shared__ float As[2][16][64];
    __shared__ float Bs[2][16][48];
    int tid = threadIdx.x;
    int m0 = blockIdx.x * 64;
    int tm = tid >> 4;          // 0..15 -> 4 rows each
    int tn = tid & 15;          // 0..15 -> 3 cols each
    int lrow = tid >> 2;        // 0..63
    int lkq  = tid & 3;         // 0..3

    float acc[4][3];
#pragma unroll
    for (int i = 0; i < 4; i++)
#pragma unroll
        for (int j = 0; j < 3; j++) acc[i][j] = 0.f;

    float4 ra, rb;
#define XLDG(k0)                                                              \
    {                                                                         \
        ra = (m0 + lrow < M)                                                  \
            ? *(const float4*)(A + (long)(m0+lrow)*DI_ + (k0) + lkq*4)        \
            : make_float4(0.f,0.f,0.f,0.f);                                   \
        rb = make_float4(0.f,0.f,0.f,0.f);                                    \
        if (tid < 192 && lrow < 44)                                           \
            rb = *(const float4*)(Bm + (long)lrow*DI_ + (k0) + lkq*4);        \
    }
#define XSTS(buf)                                                             \
    {                                                                         \
        As[buf][lkq*4+0][lrow] = ra.x; As[buf][lkq*4+1][lrow] = ra.y;         \
        As[buf][lkq*4+2][lrow] = ra.z; As[buf][lkq*4+3][lrow] = ra.w;         \
        if (tid < 192) {                                                      \
            Bs[buf][lkq*4+0][lrow] = rb.x; Bs[buf][lkq*4+1][lrow] = rb.y;     \
            Bs[buf][lkq*4+2][lrow] = rb.z; Bs[buf][lkq*4+3][lrow] = rb.w;     \
        }                                                                     \
    }
#define XCOMP(buf)                                                            \
    {                                                                         \
        _Pragma("unroll")                                                     \
        for (int kk = 0; kk < 16; kk++) {                                     \
            float a4[4];                                                      \
            *(float4*)a4 = *(const float4*)&As[buf][kk][tm*4];                \
            float b0 = Bs[buf][kk][tn*3+0];                                   \
            float b1 = Bs[buf][kk][tn*3+1];                                   \
            float b2 = Bs[buf][kk][tn*3+2];                                   \
            _Pragma("unroll")                                                 \
            for (int i = 0; i < 4; i++) {                                     \
                acc[i][0] = fmaf(a4[i], b0, acc[i][0]);                       \
                acc[i][1] = fmaf(a4[i], b1, acc[i][1]);                       \
                acc[i][2] = fmaf(a4[i], b2, acc[i][2]);                       \
            }                                                                 \
        }                                                                     \
    }

    XLDG(0); XSTS(0);
    __syncthreads();
    int buf = 0;
    for (int k0 = 16; k0 < DI_; k0 += 16) {
        XLDG(k0);
        XCOMP(buf);
        XSTS(buf ^ 1);
        __syncthreads();
        buf ^= 1;
    }
    XCOMP(buf);

#pragma unroll
    for (int i = 0; i < 4; i++) {
        int row = m0 + tm*4 + i;
        if (row < M) {
#pragma unroll
            for (int j = 0; j < 3; j++)
                C[(long)row*XP_ + tn*3 + j] = acc[i][j];
        }
    }
#undef XLDG
#undef XSTS
#undef XCOMP
}

// ---------------- causal depthwise conv(4) + silu, 4 channels/thread ----------------
__global__ void k_conv(const float* __restrict__ cw, const float* __restrict__ cb)
{
    int idx = blockIdx.x*blockDim.x + threadIdx.x;
    if (idx >= NTOK_*(DI_/4)) return;
    int c4 = idx % (DI_/4);
    int t  = idx / (DI_/4);
    int l  = t % L_;
    int d  = c4*4;

    float acc[4];
    *(float4*)acc = *(const float4*)(cb + d);
    float wv[4][4];          // wv[i][k] : channel d+i, tap k
#pragma unroll
    for (int i = 0; i < 4; i++)
        *(float4*)wv[i] = *(const float4*)(cw + (d+i)*4);
#pragma unroll
    for (int k = 0; k < 4; k++) {
        int ls = l - 3 + k;
        if (ls >= 0) {
            float x[4];
            *(float4*)x = *(const float4*)(g_xz + (long)(t-3+k)*(2*DI_) + d);
#pragma unroll
            for (int i = 0; i < 4; i++)
                acc[i] = fmaf(x[i], wv[i][k], acc[i]);
        }
    }
    float o[4];
#pragma unroll
    for (int i = 0; i < 4; i++)
        o[i] = acc[i] / (1.f + __expf(-acc[i]));
    *(float4*)(g_xc + (long)t*DI_ + d) = *(float4*)o;
}

// =========================================================================
// Fused selective scan with software-pipelined loads (exact R6 version).
// 4 threads per (b,d) channel; grid (12, 32), block 128.
// =========================================================================
__global__ __launch_bounds__(128)
void k_scan(const float* __restrict__ A_log, const float* __restrict__ Dsk,
            const float* __restrict__ dtw_g, const float* __restrict__ dtb_g)
{
    int local = blockIdx.x*128 + threadIdx.x;   // 0..1535
    int d = local >> 2;                          // 0..383
    int q = local & 3;                           // quarter of states
    int b = blockIdx.y;

    float a[4];
#pragma unroll
    for (int n = 0; n < 4; n++) a[n] = -__expf(A_log[d*NS_ + q*4 + n]);
    float w[NR_];
#pragma unroll
    for (int r = 0; r < NR_; r++) w[r] = dtw_g[d*NR_ + r];
    float dtb = dtb_g[d];
    float dsk = Dsk[d];
    float h[4] = {0.f, 0.f, 0.f, 0.f};

    long tbase = (long)b * L_;
    const float4* xr = (const float4*)(g_xdb + tbase*XP_);
    float4 r0 = xr[0], r1 = xr[1], r2 = xr[2];
    float4 Bq = xr[3+q], Cq = xr[7+q];
    float u = g_xc[tbase*DI_ + d];
    float z = g_xz[tbase*(2*DI_) + DI_ + d];

    for (int l = 0; l < L_; l++) {
        long t = tbase + l;
        long t2 = tbase + ((l+1 < L_) ? l+1 : l);
        const float4* x2 = (const float4*)(g_xdb + t2*XP_);
        float4 p0 = x2[0], p1 = x2[1], p2 = x2[2];
        float4 pB = x2[3+q], pC = x2[7+q];
        float pu = g_xc[t2*DI_ + d];
        float pz = g_xz[t2*(2*DI_) + DI_ + d];

        float a0 = dtb, a1 = 0.f;
        a0 = fmaf(r0.x, w[0], a0); a1 = fmaf(r0.y, w[1],  a1);
        a0 = fmaf(r0.z, w[2], a0); a1 = fmaf(r0.w, w[3],  a1);
        a0 = fmaf(r1.x, w[4], a0); a1 = fmaf(r1.y, w[5],  a1);
        a0 = fmaf(r1.z, w[6], a0); a1 = fmaf(r1.w, w[7],  a1);
        a0 = fmaf(r2.x, w[8], a0); a1 = fmaf(r2.y, w[9],  a1);
        a0 = fmaf(r2.z, w[10],a0); a1 = fmaf(r2.w, w[11], a1);
        float acc = a0 + a1;
        float dt = fmaxf(acc, 0.f) + __logf(1.f + __expf(-fabsf(acc)));
        float du = dt * u;

        float Bv[4] = {Bq.x, Bq.y, Bq.z, Bq.w};
        float Cv[4] = {Cq.x, Cq.y, Cq.z, Cq.w};
        float y = 0.f;
#pragma unroll
        for (int n = 0; n < 4; n++) {
            float dA = __expf(dt * a[n]);
            h[n] = fmaf(h[n], dA, du * Bv[n]);
            y = fmaf(h[n], Cv[n], y);
        }
        y += __shfl_xor_sync(0xffffffffu, y, 1);
        y += __shfl_xor_sync(0xffffffffu, y, 2);
        if (q == 0) {
            float sg = z / (1.f + __expf(-z));
            g_y[t*DI_ + d] = (y + u*dsk) * sg;
        }
        r0 = p0; r1 = p1; r2 = p2; Bq = pB; Cq = pC; u = pu; z = pz;
    }
}

// ---------------- layer-3 out_proj: only last tokens matter ----------------
__global__ void k_outlast(const float* __restrict__ ow)
{
    int b = blockIdx.x;
    int e = threadIdx.x;         // 192
    __shared__ float ys[DI_];
    int t = b*L_ + (L_-1);
    for (int i = e; i < DI_; i += E_) ys[i] = g_y[(long)t*DI_ + i];
    __syncthreads();
    float acc = 0.f;
    const float* w = ow + e*DI_;
#pragma unroll 4
    for (int d2 = 0; d2 < DI_; d2++) acc = fmaf(ys[d2], w[d2], acc);
    g_x[t*E_ + e] = acc;
}

// ---------------- final rmsnorm (last token) + classifier head ----------------
__global__ void k_final(const float* __restrict__ nfw, const float* __restrict__ hw,
                        const float* __restrict__ hb, float* __restrict__ out)
{
    int b = blockIdx.x;
    int e = threadIdx.x;         // 192
    int t = b*L_ + (L_-1);
    float r = g_x[t*E_ + e] + g_res[t*E_ + e];
    float s = r*r;
#pragma unroll
    for (int o = 16; o > 0; o >>= 1) s += __shfl_down_sync(0xffffffffu, s, o);
    __shared__ float ws[6];
    __shared__ float s_inv;
    __shared__ float vs[E_];
    int w = e >> 5, lane = e & 31;
    if (lane == 0) ws[w] = s;
    __syncthreads();
    if (e == 0) {
        float tot = ws[0]+ws[1]+ws[2]+ws[3]+ws[4]+ws[5];
        s_inv = rsqrtf(tot * (1.0f/E_) + EPS_);
    }
    __syncthreads();
    vs[e] = r * s_inv * nfw[e];
    __syncthreads();
    if (e < 20) {
        float acc = hb[e];
        const float* wr = hw + e*E_;
#pragma unroll 4
        for (int j = 0; j < E_; j++) acc = fmaf(vs[j], wr[j], acc);
        out[b*20 + e] = acc;
    }
}

// ---------------- launch ----------------
extern "C" void kernel_launch(void* const* d_in, const int* in_sizes, int n_in,
                              void* d_out, int out_size)
{
    const float* imgs      = (const float*)d_in[0];
    const float* patch_w   = (const float*)d_in[1];
    const float* patch_b   = (const float*)d_in[2];
    const float* cls_token = (const float*)d_in[3];
    const float* pos_embed = (const float*)d_in[4];
    const float* cnn_w     = (const float*)d_in[5];
    const float* cnn_b     = (const float*)d_in[6];
    const float* norm_w    = (const float*)d_in[7];
    const float* in_proj_w = (const float*)d_in[8];
    const float* conv_w    = (const float*)d_in[9];
    const float* conv_b    = (const float*)d_in[10];
    const float* x_proj_w  = (const float*)d_in[11];
    const float* dt_proj_w = (const float*)d_in[12];
    const float* dt_proj_b = (const float*)d_in[13];
    const float* A_log     = (const float*)d_in[14];
    const float* D_skip    = (const float*)d_in[15];
    const float* out_proj_w= (const float*)d_in[16];
    const float* norm_f_w  = (const float*)d_in[17];
    const float* head_w    = (const float*)d_in[18];
    const float* head_b    = (const float*)d_in[19];
    float* out = (float*)d_out;

    float *p_hn, *p_xz, *p_xdb, *p_y, *p_x, *p_xc;
    __nv_bfloat16 *p_a2, *p_a2o, *p_b2, *p_b2o;
    cudaGetSymbolAddress((void**)&p_hn,  g_hn);
    cudaGetSymbolAddress((void**)&p_xz,  g_xz);
    cudaGetSymbolAddress((void**)&p_xdb, g_xdb);
    cudaGetSymbolAddress((void**)&p_y,   g_y);
    cudaGetSymbolAddress((void**)&p_x,   g_x);
    cudaGetSymbolAddress((void**)&p_xc,  g_xc);
    cudaGetSymbolAddress((void**)&p_a2,  g_a2);
    cudaGetSymbolAddress((void**)&p_a2o, g_a2o);
    cudaGetSymbolAddress((void**)&p_b2,  g_b2);
    cudaGetSymbolAddress((void**)&p_b2o, g_b2o);

    // 1: embed
    k_embed<<<(NTOK_*E_ + 255)/256, 256>>>(imgs, patch_w, patch_b, cls_token,
                                           pos_embed, cnn_w, cnn_b);
    // 2-3: batched vectorized weight splits (all layers at once)
    k_wcvt<<<dim3((768*E_/4+255)/256, 4), 256>>>(in_proj_w, p_b2, 768, E_,
                                                 (long)768*E_, (long)768*3*E_);
    k_wcvt<<<dim3((E_*DI_/4+255)/256, 3), 256>>>(out_proj_w, p_b2o, E_, DI_,
                                                 (long)E_*DI_, (long)E_*3*DI_);

    const int MGRID = (NTOK_ + 127) / 128;   // 101
    dim3 gIn (6, MGRID);    // N tiles of 128 over 768
    dim3 gOut(3, MGRID);    // N tiles of 64 over 192
    int ew_blocks  = (NTOK_*(DI_/4) + 255)/256;
    int xp_blocks  = (NTOK_ + 63) / 64;      // 201
    int acvt_in_b  = (NTOK_*(E_/4)  + 255)/256;
    int acvt_out_b = (NTOK_*(DI_/4) + 255)/256;

    for (int i = 0; i < 4; i++) {
        k_resnorm<<<NTOK_/2, 384>>>(norm_w + i*E_, i == 0);
        k_acvt<<<acvt_in_b, 256>>>(p_hn, p_a2, NTOK_, E_);
        hgemm<128,256><<<gIn, 256>>>(p_a2, p_b2 + (long)i*768*3*E_, p_xz,
                                     NTOK_, 3*E_, 2*DI_, 2*DI_);
        k_conv<<<ew_blocks, 256>>>(conv_w + (long)i*DI_*4, conv_b + i*DI_);
        sgemm_xp<<<xp_blocks, 256>>>(p_xc, x_proj_w + (long)i*(NR_+2*NS_)*DI_,
                                     p_xdb, NTOK_);
        k_scan<<<dim3(12, BATCH_), 128>>>(A_log + (long)i*DI_*NS_, D_skip + i*DI_,
                                          dt_proj_w + (long)i*DI_*NR_,
                                          dt_proj_b + i*DI_);
        if (i < 3) {
            k_acvt<<<acvt_out_b, 256>>>(p_y, p_a2o, NTOK_, DI_);
            hgemm<64,128><<<gOut, 128>>>(p_a2o, p_b2o + (long)i*E_*3*DI_, p_x,
                                         NTOK_, 3*DI_, E_, E_);
        } else {
            k_outlast<<<BATCH_, E_>>>(out_proj_w + (long)i*E_*DI_);
        }
    }
    k_final<<<BATCH_, E_>>>(norm_f_w, head_w, head_b, out);
}

// round 14
// speedup vs baseline: 1.0437x; 1.0016x over previous
#include <cuda_runtime.h>
#include <cuda_bf16.h>
#include <cstdint>

// ---------------- constants ----------------
#define E_    192
#define DI_   384
#define NS_   16
#define NR_   12
#define L_    401
#define BATCH_ 32
#define NTOK_ (BATCH_*L_)     // 12832
#define XP_   48              // padded xdb row stride (44 used)
#define EPS_  1e-5f

// ---------------- scratch (static device globals; no allocation) ----------------
__device__ float g_x  [NTOK_*E_];        // hidden (out_proj output)
__device__ float g_res[NTOK_*E_];        // residual
__device__ float g_xz [NTOK_*2*DI_];     // in_proj out (xm | z)
__device__ float g_xc [NTOK_*DI_];       // conv+silu out
__device__ float g_xdb[NTOK_*XP_];       // x_proj out (dt_r | B | C), padded
__device__ float g_y  [NTOK_*DI_];       // scan output (gated)

// bf16 hi/lo packed operands for tensor-core GEMMs
__device__ __nv_bfloat16 g_a2 [(long)NTOK_*3*E_];     // in_proj A'  [M, 576]
__device__ __nv_bfloat16 g_a2o[(long)NTOK_*3*DI_];    // out_proj A' [M, 1152]
__device__ __nv_bfloat16 g_b2 [4ll*768*3*E_];         // in_proj  W' 4 layers
__device__ __nv_bfloat16 g_b2o[3ll*E_*3*DI_];         // out_proj W' 3 layers

// ---------------- warp-MMA helpers (compute_103-safe PTX) ----------------
__device__ __forceinline__ uint32_t smem_u32(const void* p) {
    uint32_t a;
    asm("{ .reg .u64 t; cvta.to.shared.u64 t, %1; cvt.u32.u64 %0, t; }"
        : "=r"(a) : "l"(p));
    return a;
}
__device__ __forceinline__ void ldsm4(uint32_t* r, uint32_t addr) {
    asm volatile("ldmatrix.sync.aligned.m8n8.x4.shared.b16 {%0,%1,%2,%3}, [%4];"
        : "=r"(r[0]), "=r"(r[1]), "=r"(r[2]), "=r"(r[3]) : "r"(addr));
}
__device__ __forceinline__ void mma_bf16(float* c, const uint32_t* a, const uint32_t* b) {
    asm volatile("mma.sync.aligned.m16n8k16.row.col.f32.bf16.bf16.f32 "
        "{%0,%1,%2,%3}, {%4,%5,%6,%7}, {%8,%9}, {%0,%1,%2,%3};"
        : "+f"(c[0]), "+f"(c[1]), "+f"(c[2]), "+f"(c[3])
        : "r"(a[0]), "r"(a[1]), "r"(a[2]), "r"(a[3]), "r"(b[0]), "r"(b[1]));
}
__device__ __forceinline__ void split_a(float x, __nv_bfloat16* dst) {
    __nv_bfloat16 hi = __float2bfloat16(x);
    __nv_bfloat16 lo = __float2bfloat16(x - __bfloat162float(hi));
    dst[0]      = hi;     // A side layout: [hi | lo | hi]
    dst[E_]     = lo;
    dst[2*E_]   = hi;
}

// ---------------- batched, vectorized weight split (B side: hi|hi|lo) ----------------
__global__ void k_wcvt(const float* __restrict__ src, __nv_bfloat16* __restrict__ dst,
                       int R, int K, long lsrc, long ldst)
{
    int idx = blockIdx.x*blockDim.x + threadIdx.x;
    int nk4 = K >> 2;
    if (idx >= R*nk4) return;
    int lay = blockIdx.y;
    int r = idx / nk4, k4 = (idx % nk4) << 2;
    float4 v = *(const float4*)(src + lay*lsrc + (long)r*K + k4);
    float vv[4] = {v.x, v.y, v.z, v.w};
    __nv_bfloat16 hi[4], lo[4];
#pragma unroll
    for (int i = 0; i < 4; i++) {
        hi[i] = __float2bfloat16(vv[i]);
        lo[i] = __float2bfloat16(vv[i] - __bfloat162float(hi[i]));
    }
    __nv_bfloat16* base = dst + lay*ldst + (long)r*3*K + k4;
    *(uint2*)(base)       = *(uint2*)hi;
    *(uint2*)(base + K)   = *(uint2*)hi;
    *(uint2*)(base + 2*K) = *(uint2*)lo;
}

// ---------------- vectorized activation split (A side: hi|lo|hi), for y ----------------
__global__ void k_acvt(const float* __restrict__ src, __nv_bfloat16* __restrict__ dst,
                       int R, int K)
{
    int idx = blockIdx.x*blockDim.x + threadIdx.x;
    int nk4 = K >> 2;
    if (idx >= R*nk4) return;
    int r = idx / nk4, k4 = (idx % nk4) << 2;
    float4 v = *(const float4*)(src + (long)r*K + k4);
    float vv[4] = {v.x, v.y, v.z, v.w};
    __nv_bfloat16 hi[4], lo[4];
#pragma unroll
    for (int i = 0; i < 4; i++) {
        hi[i] = __float2bfloat16(vv[i]);
        lo[i] = __float2bfloat16(vv[i] - __bfloat162float(hi[i]));
    }
    __nv_bfloat16* base = dst + (long)r*3*K + k4;
    *(uint2*)(base)       = *(uint2*)hi;
    *(uint2*)(base + K)   = *(uint2*)lo;
    *(uint2*)(base + 2*K) = *(uint2*)hi;
}

// ---------------- FUSED patch embed + pos + cnn + cls + rmsnorm + A-split ----------------
// One block per token, 192 threads. Produces g_res (residual) and g_a2 (split A).
__global__ __launch_bounds__(192)
void k_embed_norm(const float* __restrict__ imgs, const float* __restrict__ pw,
                  const float* __restrict__ pb,   const float* __restrict__ cls,
                  const float* __restrict__ pos,  const float* __restrict__ cw,
                  const float* __restrict__ cb,   const float* __restrict__ norm_w)
{
    int t = blockIdx.x;
    int e = threadIdx.x;
    int l = t % L_;
    int b = t / L_;
    float v;
    if (l == L_-1) {
        v = cls[e] + pos[(L_-1)*E_ + e];
    } else {
        float acc = cb[e];
        const float* w4 = pw + e*4;
#pragma unroll
        for (int k = 0; k < 3; k++) {
            int ls = l - 1 + k;
            if (ls >= 0 && ls < 400) {
                const float* im = imgs + b*1600 + ls*4;
                float pe = im[0]*w4[0] + im[1]*w4[1] + im[2]*w4[2] + im[3]*w4[3]
                         + pb[e] + pos[ls*E_ + e];
                acc = fmaf(pe, cw[e*3 + k], acc);
            }
        }
        v = acc;
    }
    g_res[t*E_ + e] = v;

    float s = v*v;
#pragma unroll
    for (int o = 16; o > 0; o >>= 1) s += __shfl_down_sync(0xffffffffu, s, o);
    __shared__ float ws[6];
    __shared__ float s_inv;
    int w = e >> 5, lane = e & 31;
    if (lane == 0) ws[w] = s;
    __syncthreads();
    if (e == 0) {
        float tot = ws[0]+ws[1]+ws[2]+ws[3]+ws[4]+ws[5];
        s_inv = rsqrtf(tot * (1.0f/E_) + EPS_);
    }
    __syncthreads();
    float hn = v * s_inv * norm_w[e];
    split_a(hn, g_a2 + (long)t*3*E_ + e);
}

// ---------------- residual accumulate + rmsnorm + A-split (2 tokens/block) ----------------
__global__ __launch_bounds__(384)
void k_resnorm(const float* __restrict__ norm_w)
{
    int grp = threadIdx.x / 192;     // 0..1
    int e   = threadIdx.x % 192;
    int t = blockIdx.x*2 + grp;      // NTOK_ even -> always valid
    float r = g_x[t*E_ + e] + g_res[t*E_ + e];
    g_res[t*E_ + e] = r;
    float s = r*r;
#pragma unroll
    for (int o = 16; o > 0; o >>= 1) s += __shfl_down_sync(0xffffffffu, s, o);
    __shared__ float ws[12];
    __shared__ float s_inv[2];
    int w = threadIdx.x >> 5, lane = threadIdx.x & 31;
    if (lane == 0) ws[w] = s;
    __syncthreads();
    if (e == 0) {
        int b0 = grp*6;
        float tot = ws[b0]+ws[b0+1]+ws[b0+2]+ws[b0+3]+ws[b0+4]+ws[b0+5];
        s_inv[grp] = rsqrtf(tot * (1.0f/E_) + EPS_);
    }
    __syncthreads();
    float hn = r * s_inv[grp] * norm_w[e];
    split_a(hn, g_a2 + (long)t*3*E_ + e);
}

// =========================================================================
// HMMA bf16 GEMM: C[M,Nn] = A2[M,Keff] * B2[Nn,Keff]^T (fp32 accum)
// CTA tile 128 x BN, BK=32, double-buffered smem, warp tile 64x32.
// =========================================================================
template<int BN, int NTH>
__global__ __launch_bounds__(NTH)
void hgemm(const __nv_bfloat16* __restrict__ A2, const __nv_bfloat16* __restrict__ B2,
           float* __restrict__ C, int M, int Keff, int Nn, int ldc)
{
    constexpr int WN = BN/32;                 // warps along N
    constexpr int NLA = 512/NTH;              // A uint4 loads per thread
    constexpr int NLB = (BN*4)/NTH;           // B uint4 loads per thread
    constexpr int ASTRIDE = 40;               // bf16 elems per smem row
    __shared__ __align__(16) __nv_bfloat16 sA[2][128][ASTRIDE];
    __shared__ __align__(16) __nv_bfloat16 sB[2][BN][ASTRIDE];
    constexpr uint32_t ABUF = 128*ASTRIDE*2;  // bytes per A buffer
    constexpr uint32_t BBUF = BN*ASTRIDE*2;

    int tid = threadIdx.x, wid = tid >> 5, lane = tid & 31;
    int wm = wid / WN, wn = wid % WN;
    int m0 = blockIdx.y * 128;
    int n0 = blockIdx.x * BN;

    uint32_t a_addr[4], b_addr[2];
#pragma unroll
    for (int am = 0; am < 4; am++) {
        int row = wm*64 + am*16 + (lane & 15);
        int colb = (lane >> 4) * 16;
        a_addr[am] = smem_u32(&sA[0][row][0]) + colb;
    }
#pragma unroll
    for (int p = 0; p < 2; p++) {
        int row = wn*32 + p*16 + (lane & 7) + ((lane >> 4) << 3);
        int colb = ((lane >> 3) & 1) * 16;
        b_addr[p] = smem_u32(&sB[0][row][0]) + colb;
    }

    float c[4][4][4];
#pragma unroll
    for (int i = 0; i < 4; i++)
#pragma unroll
        for (int j = 0; j < 4; j++)
#pragma unroll
            for (int k = 0; k < 4; k++) c[i][j][k] = 0.f;

    uint4 ra[NLA], rb[NLB];

#define H_LDG(k0)                                                             \
    {                                                                         \
        _Pragma("unroll")                                                     \
        for (int i = 0; i < NLA; i++) {                                       \
            int g = tid + i*NTH;                                              \
            int row = g >> 2, seg = g & 3;                                    \
            ra[i] = (m0 + row < M)                                            \
                ? *(const uint4*)(A2 + (long)(m0+row)*Keff + (k0) + seg*8)    \
                : make_uint4(0u,0u,0u,0u);                                    \
        }                                                                     \
        _Pragma("unroll")                                                     \
        for (int i = 0; i < NLB; i++) {                                       \
            int g = tid + i*NTH;                                              \
            int row = g >> 2, seg = g & 3;                                    \
            rb[i] = *(const uint4*)(B2 + (long)(n0+row)*Keff + (k0) + seg*8); \
        }                                                                     \
    }
#define H_STS(buf)                                                            \
    {                                                                         \
        _Pragma("unroll")                                                     \
        for (int i = 0; i < NLA; i++) {                                       \
            int g = tid + i*NTH;                                              \
            int row = g >> 2, seg = g & 3;                                    \
            *(uint4*)&sA[buf][row][seg*8] = ra[i];                            \
        }                                                                     \
        _Pragma("unroll")                                                     \
        for (int i = 0; i < NLB; i++) {                                       \
            int g = tid + i*NTH;                                              \
            int row = g >> 2, seg = g & 3;                                    \
            *(uint4*)&sB[buf][row][seg*8] = rb[i];                            \
        }                                                                     \
    }
#define H_COMP(buf)                                                           \
    {                                                                         \
        uint32_t aoff = (buf)*ABUF, boff = (buf)*BBUF;                        \
        _Pragma("unroll")                                                     \
        for (int ks = 0; ks < 2; ks++) {                                      \
            uint32_t af[4][4], bf[2][4];                                      \
            _Pragma("unroll")                                                 \
            for (int am = 0; am < 4; am++)                                    \
                ldsm4(af[am], a_addr[am] + aoff + ks*32);                     \
            _Pragma("unroll")                                                 \
            for (int p = 0; p < 2; p++)                                       \
                ldsm4(bf[p], b_addr[p] + boff + ks*32);                       \
            _Pragma("unroll")                                                 \
            for (int am = 0; am < 4; am++)                                    \
                _Pragma("unroll")                                             \
                for (int bn = 0; bn < 4; bn++)                                \
                    mma_bf16(c[am][bn], af[am], &bf[bn>>1][(bn&1)*2]);        \
        }                                                                     \
    }

    int nchunk = Keff >> 5;
    H_LDG(0);
    H_STS(0);
    __syncthreads();
    for (int ck = 0; ck < nchunk; ck++) {
        if (ck + 1 < nchunk) H_LDG((ck+1)*32);
        H_COMP(ck & 1);
        if (ck + 1 < nchunk) {
            H_STS((ck+1) & 1);
        }
        __syncthreads();
    }

    // epilogue: direct fp32 stores
#pragma unroll
    for (int am = 0; am < 4; am++) {
        int r0 = m0 + wm*64 + am*16 + (lane >> 2);
        int r1 = r0 + 8;
#pragma unroll
        for (int bn = 0; bn < 4; bn++) {
            int col = n0 + wn*32 + bn*8 + (lane & 3)*2;
            if (col < Nn) {
                if (r0 < M) *(float2*)(C + (long)r0*ldc + col) = make_float2(c[am][bn][0], c[am][bn][1]);
                if (r1 < M) *(float2*)(C + (long)r1*ldc + col) = make_float2(c[am][bn][2], c[am][bn][3]);
            }
        }
    }
#undef H_LDG
#undef H_STS
#undef H_COMP
}

// =========================================================================
// x_proj SGEMM (fp32): C[M,48(44 used)] = A[M,384] * B[44,384]^T
// 64x48 tile, 256 threads, double-buffered. 201 CTAs.
// =========================================================================
__global__ __launch_bounds__(256)
void sgemm_xp(const float* __restrict__ A, const float* __restrict__ Bm,
              float* __restrict__ C, int M)
{
    __shared__ float As[2][16][64];
    __shared__ float Bs[2][16][48];
    int tid = threadIdx.x;
    int m0 = blockIdx.x * 64;
    int tm = tid >> 4;          // 0..15 -> 4 rows each
    int tn = tid & 15;          // 0..15 -> 3 cols each
    int lrow = tid >> 2;        // 0..63
    int lkq  = tid & 3;         // 0..3

    float acc[4][3];
#pragma unroll
    for (int i = 0; i < 4; i++)
#pragma unroll
        for (int j = 0; j < 3; j++) acc[i][j] = 0.f;

    float4 ra, rb;
#define XLDG(k0)                                                              \
    {                                                                         \
        ra = (m0 + lrow < M)                                                  \
            ? *(const float4*)(A + (long)(m0+lrow)*DI_ + (k0) + lkq*4)        \
            : make_float4(0.f,0.f,0.f,0.f);                                   \
        rb = make_float4(0.f,0.f,0.f,0.f);                                    \
        if (tid < 192 && lrow < 44)                                           \
            rb = *(const float4*)(Bm + (long)lrow*DI_ + (k0) + lkq*4);        \
    }
#define XSTS(buf)                                                             \
    {                                                                         \
        As[buf][lkq*4+0][lrow] = ra.x; As[buf][lkq*4+1][lrow] = ra.y;         \
        As[buf][lkq*4+2][lrow] = ra.z; As[buf][lkq*4+3][lrow] = ra.w;         \
        if (tid < 192) {                                                      \
            Bs[buf][lkq*4+0][lrow] = rb.x; Bs[buf][lkq*4+1][lrow] = rb.y;     \
            Bs[buf][lkq*4+2][lrow] = rb.z; Bs[buf][lkq*4+3][lrow] = rb.w;     \
        }                                                                     \
    }
#define XCOMP(buf)                                                            \
    {                                                                         \
        _Pragma("unroll")                                                     \
        for (int kk = 0; kk < 16; kk++) {                                     \
            float a4[4];                                                      \
            *(float4*)a4 = *(const float4*)&As[buf][kk][tm*4];                \
            float b0 = Bs[buf][kk][tn*3+0];                                   \
            float b1 = Bs[buf][kk][tn*3+1];                                   \
            float b2 = Bs[buf][kk][tn*3+2];                                   \
            _Pragma("unroll")                                                 \
            for (int i = 0; i < 4; i++) {                                     \
                acc[i][0] = fmaf(a4[i], b0, acc[i][0]);                       \
                acc[i][1] = fmaf(a4[i], b1, acc[i][1]);                       \
                acc[i][2] = fmaf(a4[i], b2, acc[i][2]);                       \
            }                                                                 \
        }                                                                     \
    }

    XLDG(0); XSTS(0);
    __syncthreads();
    int buf = 0;
    for (int k0 = 16; k0 < DI_; k0 += 16) {
        XLDG(k0);
        XCOMP(buf);
        XSTS(buf ^ 1);
        __syncthreads();
        buf ^= 1;
    }
    XCOMP(buf);

#pragma unroll
    for (int i = 0; i < 4; i++) {
        int row = m0 + tm*4 + i;
        if (row < M) {
#pragma unroll
            for (int j = 0; j < 3; j++)
                C[(long)row*XP_ + tn*3 + j] = acc[i][j];
        }
    }
#undef XLDG
#undef XSTS
#undef XCOMP
}

// ---------------- causal depthwise conv(4) + silu, 4 channels/thread ----------------
__global__ void k_conv(const float* __restrict__ cw, const float* __restrict__ cb)
{
    int idx = blockIdx.x*blockDim.x + threadIdx.x;
    if (idx >= NTOK_*(DI_/4)) return;
    int c4 = idx % (DI_/4);
    int t  = idx / (DI_/4);
    int l  = t % L_;
    int d  = c4*4;

    float acc[4];
    *(float4*)acc = *(const float4*)(cb + d);
    float wv[4][4];          // wv[i][k] : channel d+i, tap k
#pragma unroll
    for (int i = 0; i < 4; i++)
        *(float4*)wv[i] = *(const float4*)(cw + (d+i)*4);
#pragma unroll
    for (int k = 0; k < 4; k++) {
        int ls = l - 3 + k;
        if (ls >= 0) {
            float x[4];
            *(float4*)x = *(const float4*)(g_xz + (long)(t-3+k)*(2*DI_) + d);
#pragma unroll
            for (int i = 0; i < 4; i++)
                acc[i] = fmaf(x[i], wv[i][k], acc[i]);
        }
    }
    float o[4];
#pragma unroll
    for (int i = 0; i < 4; i++)
        o[i] = acc[i] / (1.f + __expf(-acc[i]));
    *(float4*)(g_xc + (long)t*DI_ + d) = *(float4*)o;
}

// =========================================================================
// Fused selective scan with software-pipelined loads (exact R6 version).
// 4 threads per (b,d) channel; grid (12, 32), block 128.
// =========================================================================
__global__ __launch_bounds__(128)
void k_scan(const float* __restrict__ A_log, const float* __restrict__ Dsk,
            const float* __restrict__ dtw_g, const float* __restrict__ dtb_g)
{
    int local = blockIdx.x*128 + threadIdx.x;   // 0..1535
    int d = local >> 2;                          // 0..383
    int q = local & 3;                           // quarter of states
    int b = blockIdx.y;

    float a[4];
#pragma unroll
    for (int n = 0; n < 4; n++) a[n] = -__expf(A_log[d*NS_ + q*4 + n]);
    float w[NR_];
#pragma unroll
    for (int r = 0; r < NR_; r++) w[r] = dtw_g[d*NR_ + r];
    float dtb = dtb_g[d];
    float dsk = Dsk[d];
    float h[4] = {0.f, 0.f, 0.f, 0.f};

    long tbase = (long)b * L_;
    const float4* xr = (const float4*)(g_xdb + tbase*XP_);
    float4 r0 = xr[0], r1 = xr[1], r2 = xr[2];
    float4 Bq = xr[3+q], Cq = xr[7+q];
    float u = g_xc[tbase*DI_ + d];
    float z = g_xz[tbase*(2*DI_) + DI_ + d];

    for (int l = 0; l < L_; l++) {
        long t = tbase + l;
        long t2 = tbase + ((l+1 < L_) ? l+1 : l);
        const float4* x2 = (const float4*)(g_xdb + t2*XP_);
        float4 p0 = x2[0], p1 = x2[1], p2 = x2[2];
        float4 pB = x2[3+q], pC = x2[7+q];
        float pu = g_xc[t2*DI_ + d];
        float pz = g_xz[t2*(2*DI_) + DI_ + d];

        float a0 = dtb, a1 = 0.f;
        a0 = fmaf(r0.x, w[0], a0); a1 = fmaf(r0.y, w[1],  a1);
        a0 = fmaf(r0.z, w[2], a0); a1 = fmaf(r0.w, w[3],  a1);
        a0 = fmaf(r1.x, w[4], a0); a1 = fmaf(r1.y, w[5],  a1);
        a0 = fmaf(r1.z, w[6], a0); a1 = fmaf(r1.w, w[7],  a1);
        a0 = fmaf(r2.x, w[8], a0); a1 = fmaf(r2.y, w[9],  a1);
        a0 = fmaf(r2.z, w[10],a0); a1 = fmaf(r2.w, w[11], a1);
        float acc = a0 + a1;
        float dt = fmaxf(acc, 0.f) + __logf(1.f + __expf(-fabsf(acc)));
        float du = dt * u;

        float Bv[4] = {Bq.x, Bq.y, Bq.z, Bq.w};
        float Cv[4] = {Cq.x, Cq.y, Cq.z, Cq.w};
        float y = 0.f;
#pragma unroll
        for (int n = 0; n < 4; n++) {
            float dA = __expf(dt * a[n]);
            h[n] = fmaf(h[n], dA, du * Bv[n]);
            y = fmaf(h[n], Cv[n], y);
        }
        y += __shfl_xor_sync(0xffffffffu, y, 1);
        y += __shfl_xor_sync(0xffffffffu, y, 2);
        if (q == 0) {
            float sg = z / (1.f + __expf(-z));
            g_y[t*DI_ + d] = (y + u*dsk) * sg;
        }
        r0 = p0; r1 = p1; r2 = p2; Bq = pB; Cq = pC; u = pu; z = pz;
    }
}

// ---------------- layer-3 out_proj: only last tokens matter ----------------
__global__ void k_outlast(const float* __restrict__ ow)
{
    int b = blockIdx.x;
    int e = threadIdx.x;         // 192
    __shared__ float ys[DI_];
    int t = b*L_ + (L_-1);
    for (int i = e; i < DI_; i += E_) ys[i] = g_y[(long)t*DI_ + i];
    __syncthreads();
    float acc = 0.f;
    const float* w = ow + e*DI_;
#pragma unroll 4
    for (int d2 = 0; d2 < DI_; d2++) acc = fmaf(ys[d2], w[d2], acc);
    g_x[t*E_ + e] = acc;
}

// ---------------- final rmsnorm (last token) + classifier head ----------------
__global__ void k_final(const float* __restrict__ nfw, const float* __restrict__ hw,
                        const float* __restrict__ hb, float* __restrict__ out)
{
    int b = blockIdx.x;
    int e = threadIdx.x;         // 192
    int t = b*L_ + (L_-1);
    float r = g_x[t*E_ + e] + g_res[t*E_ + e];
    float s = r*r;
#pragma unroll
    for (int o = 16; o > 0; o >>= 1) s += __shfl_down_sync(0xffffffffu, s, o);
    __shared__ float ws[6];
    __shared__ float s_inv;
    __shared__ float vs[E_];
    int w = e >> 5, lane = e & 31;
    if (lane == 0) ws[w] = s;
    __syncthreads();
    if (e == 0) {
        float tot = ws[0]+ws[1]+ws[2]+ws[3]+ws[4]+ws[5];
        s_inv = rsqrtf(tot * (1.0f/E_) + EPS_);
    }
    __syncthreads();
    vs[e] = r * s_inv * nfw[e];
    __syncthreads();
    if (e < 20) {
        float acc = hb[e];
        const float* wr = hw + e*E_;
#pragma unroll 4
        for (int j = 0; j < E_; j++) acc = fmaf(vs[j], wr[j], acc);
        out[b*20 + e] = acc;
    }
}

// ---------------- launch ----------------
extern "C" void kernel_launch(void* const* d_in, const int* in_sizes, int n_in,
                              void* d_out, int out_size)
{
    const float* imgs      = (const float*)d_in[0];
    const float* patch_w   = (const float*)d_in[1];
    const float* patch_b   = (const float*)d_in[2];
    const float* cls_token = (const float*)d_in[3];
    const float* pos_embed = (const float*)d_in[4];
    const float* cnn_w     = (const float*)d_in[5];
    const float* cnn_b     = (const float*)d_in[6];
    const float* norm_w    = (const float*)d_in[7];
    const float* in_proj_w = (const float*)d_in[8];
    const float* conv_w    = (const float*)d_in[9];
    const float* conv_b    = (const float*)d_in[10];
    const float* x_proj_w  = (const float*)d_in[11];
    const float* dt_proj_w = (const float*)d_in[12];
    const float* dt_proj_b = (const float*)d_in[13];
    const float* A_log     = (const float*)d_in[14];
    const float* D_skip    = (const float*)d_in[15];
    const float* out_proj_w= (const float*)d_in[16];
    const float* norm_f_w  = (const float*)d_in[17];
    const float* head_w    = (const float*)d_in[18];
    const float* head_b    = (const float*)d_in[19];
    float* out = (float*)d_out;

    float *p_xz, *p_xdb, *p_y, *p_x, *p_xc;
    __nv_bfloat16 *p_a2, *p_a2o, *p_b2, *p_b2o;
    cudaGetSymbolAddress((void**)&p_xz,  g_xz);
    cudaGetSymbolAddress((void**)&p_xdb, g_xdb);
    cudaGetSymbolAddress((void**)&p_y,   g_y);
    cudaGetSymbolAddress((void**)&p_x,   g_x);
    cudaGetSymbolAddress((void**)&p_xc,  g_xc);
    cudaGetSymbolAddress((void**)&p_a2,  g_a2);
    cudaGetSymbolAddress((void**)&p_a2o, g_a2o);
    cudaGetSymbolAddress((void**)&p_b2,  g_b2);
    cudaGetSymbolAddress((void**)&p_b2o, g_b2o);

    // 1-2: batched vectorized weight splits (all layers at once)
    k_wcvt<<<dim3((768*E_/4+255)/256, 4), 256>>>(in_proj_w, p_b2, 768, E_,
                                                 (long)768*E_, (long)768*3*E_);
    k_wcvt<<<dim3((E_*DI_/4+255)/256, 3), 256>>>(out_proj_w, p_b2o, E_, DI_,
                                                 (long)E_*DI_, (long)E_*3*DI_);
    // 3: embed + layer-0 rmsnorm + A-split fused
    k_embed_norm<<<NTOK_, 192>>>(imgs, patch_w, patch_b, cls_token,
                                 pos_embed, cnn_w, cnn_b, norm_w);

    const int MGRID = (NTOK_ + 127) / 128;   // 101
    dim3 gIn (6, MGRID);    // N tiles of 128 over 768
    dim3 gOut(3, MGRID);    // N tiles of 64 over 192
    int ew_blocks  = (NTOK_*(DI_/4) + 255)/256;
    int xp_blocks  = (NTOK_ + 63) / 64;      // 201
    int acvt_out_b = (NTOK_*(DI_/4) + 255)/256;

    for (int i = 0; i < 4; i++) {
        if (i > 0)
            k_resnorm<<<NTOK_/2, 384>>>(norm_w + i*E_);
        // launch 4 of the whole sequence = this hgemm (layer 0) -> ncu target
        hgemm<128,256><<<gIn, 256>>>(p_a2, p_b2 + (long)i*768*3*E_, p_xz,
                                     NTOK_, 3*E_, 2*DI_, 2*DI_);
        k_conv<<<ew_blocks, 256>>>(conv_w + (long)i*DI_*4, conv_b + i*DI_);
        sgemm_xp<<<xp_blocks, 256>>>(p_xc, x_proj_w + (long)i*(NR_+2*NS_)*DI_,
                                     p_xdb, NTOK_);
        k_scan<<<dim3(12, BATCH_), 128>>>(A_log + (long)i*DI_*NS_, D_skip + i*DI_,
                                          dt_proj_w + (long)i*DI_*NR_,
                                          dt_proj_b + i*DI_);
        if (i < 3) {
            k_acvt<<<acvt_out_b, 256>>>(p_y, p_a2o, NTOK_, DI_);
            hgemm<64,128><<<gOut, 128>>>(p_a2o, p_b2o + (long)i*E_*3*DI_, p_x,
                                         NTOK_, 3*DI_, E_, E_);
        } else {
            k_outlast<<<BATCH_, E_>>>(out_proj_w + (long)i*E_*DI_);
        }
    }
    k_final<<<BATCH_, E_>>>(norm_f_w, head_w, head_b, out);
}

// round 15
// speedup vs baseline: 1.0466x; 1.0028x over previous
#include <cuda_runtime.h>
#include <cuda_bf16.h>
#include <cstdint>

// ---------------- constants ----------------
#define E_    192
#define DI_   384
#define NS_   16
#define NR_   12
#define L_    401
#define BATCH_ 32
#define NTOK_ (BATCH_*L_)     // 12832
#define XP_   48              // padded xdb row stride (44 used)
#define EPS_  1e-5f

// ---------------- scratch (static device globals; no allocation) ----------------
__device__ float g_x  [NTOK_*E_];        // hidden (out_proj output)
__device__ float g_res[NTOK_*E_];        // residual
__device__ float g_xz [NTOK_*2*DI_];     // in_proj out (xm | z)
__device__ float g_xc [NTOK_*DI_];       // conv+silu out
__device__ float g_xdb[NTOK_*XP_];       // x_proj out (dt_r | B | C), padded
__device__ float g_y  [NTOK_*DI_];       // scan output (gated)

// bf16 hi/lo packed operands for tensor-core GEMMs
__device__ __nv_bfloat16 g_a2 [(long)NTOK_*3*E_];     // in_proj A'  [M, 576]
__device__ __nv_bfloat16 g_a2o[(long)NTOK_*3*DI_];    // out_proj A' [M, 1152]
__device__ __nv_bfloat16 g_b2 [4ll*768*3*E_];         // in_proj  W' 4 layers
__device__ __nv_bfloat16 g_b2o[3ll*E_*3*DI_];         // out_proj W' 3 layers

// ---------------- warp-MMA helpers (compute_103-safe PTX) ----------------
__device__ __forceinline__ uint32_t smem_u32(const void* p) {
    uint32_t a;
    asm("{ .reg .u64 t; cvta.to.shared.u64 t, %1; cvt.u32.u64 %0, t; }"
        : "=r"(a) : "l"(p));
    return a;
}
__device__ __forceinline__ void ldsm4(uint32_t* r, uint32_t addr) {
    asm volatile("ldmatrix.sync.aligned.m8n8.x4.shared.b16 {%0,%1,%2,%3}, [%4];"
        : "=r"(r[0]), "=r"(r[1]), "=r"(r[2]), "=r"(r[3]) : "r"(addr));
}
__device__ __forceinline__ void mma_bf16(float* c, const uint32_t* a, const uint32_t* b) {
    asm volatile("mma.sync.aligned.m16n8k16.row.col.f32.bf16.bf16.f32 "
        "{%0,%1,%2,%3}, {%4,%5,%6,%7}, {%8,%9}, {%0,%1,%2,%3};"
        : "+f"(c[0]), "+f"(c[1]), "+f"(c[2]), "+f"(c[3])
        : "r"(a[0]), "r"(a[1]), "r"(a[2]), "r"(a[3]), "r"(b[0]), "r"(b[1]));
}
__device__ __forceinline__ void split_a(float x, __nv_bfloat16* dst) {
    __nv_bfloat16 hi = __float2bfloat16(x);
    __nv_bfloat16 lo = __float2bfloat16(x - __bfloat162float(hi));
    dst[0]      = hi;     // A side layout: [hi | lo | hi]
    dst[E_]     = lo;
    dst[2*E_]   = hi;
}

// ---------------- batched, vectorized weight split (B side: hi|hi|lo) ----------------
__global__ void k_wcvt(const float* __restrict__ src, __nv_bfloat16* __restrict__ dst,
                       int R, int K, long lsrc, long ldst)
{
    int idx = blockIdx.x*blockDim.x + threadIdx.x;
    int nk4 = K >> 2;
    if (idx >= R*nk4) return;
    int lay = blockIdx.y;
    int r = idx / nk4, k4 = (idx % nk4) << 2;
    float4 v = *(const float4*)(src + lay*lsrc + (long)r*K + k4);
    float vv[4] = {v.x, v.y, v.z, v.w};
    __nv_bfloat16 hi[4], lo[4];
#pragma unroll
    for (int i = 0; i < 4; i++) {
        hi[i] = __float2bfloat16(vv[i]);
        lo[i] = __float2bfloat16(vv[i] - __bfloat162float(hi[i]));
    }
    __nv_bfloat16* base = dst + lay*ldst + (long)r*3*K + k4;
    *(uint2*)(base)       = *(uint2*)hi;
    *(uint2*)(base + K)   = *(uint2*)hi;
    *(uint2*)(base + 2*K) = *(uint2*)lo;
}

// ---------------- vectorized activation split (A side: hi|lo|hi), for y ----------------
__global__ void k_acvt(const float* __restrict__ src, __nv_bfloat16* __restrict__ dst,
                       int R, int K)
{
    int idx = blockIdx.x*blockDim.x + threadIdx.x;
    int nk4 = K >> 2;
    if (idx >= R*nk4) return;
    int r = idx / nk4, k4 = (idx % nk4) << 2;
    float4 v = *(const float4*)(src + (long)r*K + k4);
    float vv[4] = {v.x, v.y, v.z, v.w};
    __nv_bfloat16 hi[4], lo[4];
#pragma unroll
    for (int i = 0; i < 4; i++) {
        hi[i] = __float2bfloat16(vv[i]);
        lo[i] = __float2bfloat16(vv[i] - __bfloat162float(hi[i]));
    }
    __nv_bfloat16* base = dst + (long)r*3*K + k4;
    *(uint2*)(base)       = *(uint2*)hi;
    *(uint2*)(base + K)   = *(uint2*)lo;
    *(uint2*)(base + 2*K) = *(uint2*)hi;
}

// ---------------- FUSED patch embed + pos + cnn + cls + rmsnorm + A-split ----------------
__global__ __launch_bounds__(192)
void k_embed_norm(const float* __restrict__ imgs, const float* __restrict__ pw,
                  const float* __restrict__ pb,   const float* __restrict__ cls,
                  const float* __restrict__ pos,  const float* __restrict__ cw,
                  const float* __restrict__ cb,   const float* __restrict__ norm_w)
{
    int t = blockIdx.x;
    int e = threadIdx.x;
    int l = t % L_;
    int b = t / L_;
    float v;
    if (l == L_-1) {
        v = cls[e] + pos[(L_-1)*E_ + e];
    } else {
        float acc = cb[e];
        const float* w4 = pw + e*4;
#pragma unroll
        for (int k = 0; k < 3; k++) {
            int ls = l - 1 + k;
            if (ls >= 0 && ls < 400) {
                const float* im = imgs + b*1600 + ls*4;
                float pe = im[0]*w4[0] + im[1]*w4[1] + im[2]*w4[2] + im[3]*w4[3]
                         + pb[e] + pos[ls*E_ + e];
                acc = fmaf(pe, cw[e*3 + k], acc);
            }
        }
        v = acc;
    }
    g_res[t*E_ + e] = v;

    float s = v*v;
#pragma unroll
    for (int o = 16; o > 0; o >>= 1) s += __shfl_down_sync(0xffffffffu, s, o);
    __shared__ float ws[6];
    __shared__ float s_inv;
    int w = e >> 5, lane = e & 31;
    if (lane == 0) ws[w] = s;
    __syncthreads();
    if (e == 0) {
        float tot = ws[0]+ws[1]+ws[2]+ws[3]+ws[4]+ws[5];
        s_inv = rsqrtf(tot * (1.0f/E_) + EPS_);
    }
    __syncthreads();
    float hn = v * s_inv * norm_w[e];
    split_a(hn, g_a2 + (long)t*3*E_ + e);
}

// ---------------- residual accumulate + rmsnorm + A-split (2 tokens/block) ----------------
__global__ __launch_bounds__(384)
void k_resnorm(const float* __restrict__ norm_w)
{
    int grp = threadIdx.x / 192;     // 0..1
    int e   = threadIdx.x % 192;
    int t = blockIdx.x*2 + grp;      // NTOK_ even -> always valid
    float r = g_x[t*E_ + e] + g_res[t*E_ + e];
    g_res[t*E_ + e] = r;
    float s = r*r;
#pragma unroll
    for (int o = 16; o > 0; o >>= 1) s += __shfl_down_sync(0xffffffffu, s, o);
    __shared__ float ws[12];
    __shared__ float s_inv[2];
    int w = threadIdx.x >> 5, lane = threadIdx.x & 31;
    if (lane == 0) ws[w] = s;
    __syncthreads();
    if (e == 0) {
        int b0 = grp*6;
        float tot = ws[b0]+ws[b0+1]+ws[b0+2]+ws[b0+3]+ws[b0+4]+ws[b0+5];
        s_inv[grp] = rsqrtf(tot * (1.0f/E_) + EPS_);
    }
    __syncthreads();
    float hn = r * s_inv[grp] * norm_w[e];
    split_a(hn, g_a2 + (long)t*3*E_ + e);
}

// =========================================================================
// hgemm2: in_proj GEMM. CTA 128x128, 128 threads, warp tile 64x64, BK=32,
// double-buffered smem. Higher arithmetic intensity (32 FLOP/smem-byte).
// N is always a multiple of 128 here (768), M guarded.
// =========================================================================
__global__ __launch_bounds__(128)
void hgemm2(const __nv_bfloat16* __restrict__ A2, const __nv_bfloat16* __restrict__ B2,
            float* __restrict__ C, int M, int Keff, int ldc)
{
    constexpr int ASTRIDE = 40;
    __shared__ __align__(16) __nv_bfloat16 sA[2][128][ASTRIDE];
    __shared__ __align__(16) __nv_bfloat16 sB[2][128][ASTRIDE];
    constexpr uint32_t BUF = 128*ASTRIDE*2;

    int tid = threadIdx.x, wid = tid >> 5, lane = tid & 31;
    int wm = wid >> 1, wn = wid & 1;
    int m0 = blockIdx.y * 128;
    int n0 = blockIdx.x * 128;

    uint32_t a_addr[4], b_addr[4];
#pragma unroll
    for (int am = 0; am < 4; am++) {
        int row = wm*64 + am*16 + (lane & 15);
        int colb = (lane >> 4) * 16;
        a_addr[am] = smem_u32(&sA[0][row][0]) + colb;
    }
#pragma unroll
    for (int p = 0; p < 4; p++) {
        int row = wn*64 + p*16 + (lane & 7) + ((lane >> 4) << 3);
        int colb = ((lane >> 3) & 1) * 16;
        b_addr[p] = smem_u32(&sB[0][row][0]) + colb;
    }

    float c[4][8][4];
#pragma unroll
    for (int i = 0; i < 4; i++)
#pragma unroll
        for (int j = 0; j < 8; j++)
#pragma unroll
            for (int k = 0; k < 4; k++) c[i][j][k] = 0.f;

    uint4 ra[4], rb[4];

#define G2_LDG(k0)                                                            \
    {                                                                         \
        _Pragma("unroll")                                                     \
        for (int i = 0; i < 4; i++) {                                         \
            int g = tid + i*128;                                              \
            int row = g >> 2, seg = g & 3;                                    \
            ra[i] = (m0 + row < M)                                            \
                ? *(const uint4*)(A2 + (long)(m0+row)*Keff + (k0) + seg*8)    \
                : make_uint4(0u,0u,0u,0u);                                    \
            rb[i] = *(const uint4*)(B2 + (long)(n0+row)*Keff + (k0) + seg*8); \
        }                                                                     \
    }
#define G2_STS(buf)                                                           \
    {                                                                         \
        _Pragma("unroll")                                                     \
        for (int i = 0; i < 4; i++) {                                         \
            int g = tid + i*128;                                              \
            int row = g >> 2, seg = g & 3;                                    \
            *(uint4*)&sA[buf][row][seg*8] = ra[i];                            \
            *(uint4*)&sB[buf][row][seg*8] = rb[i];                            \
        }                                                                     \
    }
#define G2_COMP(buf)                                                          \
    {                                                                         \
        uint32_t off = (buf)*BUF;                                             \
        _Pragma("unroll")                                                     \
        for (int ks = 0; ks < 2; ks++) {                                      \
            uint32_t af[4][4], bf[4][4];                                      \
            _Pragma("unroll")                                                 \
            for (int am = 0; am < 4; am++)                                    \
                ldsm4(af[am], a_addr[am] + off + ks*32);                      \
            _Pragma("unroll")                                                 \
            for (int p = 0; p < 4; p++)                                       \
                ldsm4(bf[p], b_addr[p] + off + ks*32);                        \
            _Pragma("unroll")                                                 \
            for (int am = 0; am < 4; am++)                                    \
                _Pragma("unroll")                                             \
                for (int bn = 0; bn < 8; bn++)                                \
                    mma_bf16(c[am][bn], af[am], &bf[bn>>1][(bn&1)*2]);        \
        }                                                                     \
    }

    int nchunk = Keff >> 5;
    G2_LDG(0);
    G2_STS(0);
    __syncthreads();
    for (int ck = 0; ck < nchunk; ck++) {
        if (ck + 1 < nchunk) G2_LDG((ck+1)*32);
        G2_COMP(ck & 1);
        if (ck + 1 < nchunk) G2_STS((ck+1) & 1);
        __syncthreads();
    }

    // epilogue
#pragma unroll
    for (int am = 0; am < 4; am++) {
        int r0 = m0 + wm*64 + am*16 + (lane >> 2);
        int r1 = r0 + 8;
#pragma unroll
        for (int bn = 0; bn < 8; bn++) {
            int col = n0 + wn*64 + bn*8 + (lane & 3)*2;
            if (r0 < M) *(float2*)(C + (long)r0*ldc + col) = make_float2(c[am][bn][0], c[am][bn][1]);
            if (r1 < M) *(float2*)(C + (long)r1*ldc + col) = make_float2(c[am][bn][2], c[am][bn][3]);
        }
    }
#undef G2_LDG
#undef G2_STS
#undef G2_COMP
}

// =========================================================================
// HMMA bf16 GEMM (out_proj): CTA 128 x BN, BK=32, warp tile 64x32.
// =========================================================================
template<int BN, int NTH>
__global__ __launch_bounds__(NTH)
void hgemm(const __nv_bfloat16* __restrict__ A2, const __nv_bfloat16* __restrict__ B2,
           float* __restrict__ C, int M, int Keff, int Nn, int ldc)
{
    constexpr int WN = BN/32;                 // warps along N
    constexpr int NLA = 512/NTH;              // A uint4 loads per thread
    constexpr int NLB = (BN*4)/NTH;           // B uint4 loads per thread
    constexpr int ASTRIDE = 40;               // bf16 elems per smem row
    __shared__ __align__(16) __nv_bfloat16 sA[2][128][ASTRIDE];
    __shared__ __align__(16) __nv_bfloat16 sB[2][BN][ASTRIDE];
    constexpr uint32_t ABUF = 128*ASTRIDE*2;  // bytes per A buffer
    constexpr uint32_t BBUF = BN*ASTRIDE*2;

    int tid = threadIdx.x, wid = tid >> 5, lane = tid & 31;
    int wm = wid / WN, wn = wid % WN;
    int m0 = blockIdx.y * 128;
    int n0 = blockIdx.x * BN;

    uint32_t a_addr[4], b_addr[2];
#pragma unroll
    for (int am = 0; am < 4; am++) {
        int row = wm*64 + am*16 + (lane & 15);
        int colb = (lane >> 4) * 16;
        a_addr[am] = smem_u32(&sA[0][row][0]) + colb;
    }
#pragma unroll
    for (int p = 0; p < 2; p++) {
        int row = wn*32 + p*16 + (lane & 7) + ((lane >> 4) << 3);
        int colb = ((lane >> 3) & 1) * 16;
        b_addr[p] = smem_u32(&sB[0][row][0]) + colb;
    }

    float c[4][4][4];
#pragma unroll
    for (int i = 0; i < 4; i++)
#pragma unroll
        for (int j = 0; j < 4; j++)
#pragma unroll
            for (int k = 0; k < 4; k++) c[i][j][k] = 0.f;

    uint4 ra[NLA], rb[NLB];

#define H_LDG(k0)                                                             \
    {                                                                         \
        _Pragma("unroll")                                                     \
        for (int i = 0; i < NLA; i++) {                                       \
            int g = tid + i*NTH;                                              \
            int row = g >> 2, seg = g & 3;                                    \
            ra[i] = (m0 + row < M)                                            \
                ? *(const uint4*)(A2 + (long)(m0+row)*Keff + (k0) + seg*8)    \
                : make_uint4(0u,0u,0u,0u);                                    \
        }                                                                     \
        _Pragma("unroll")                                                     \
        for (int i = 0; i < NLB; i++) {                                       \
            int g = tid + i*NTH;                                              \
            int row = g >> 2, seg = g & 3;                                    \
            rb[i] = *(const uint4*)(B2 + (long)(n0+row)*Keff + (k0) + seg*8); \
        }                                                                     \
    }
#define H_STS(buf)                                                            \
    {                                                                         \
        _Pragma("unroll")                                                     \
        for (int i = 0; i < NLA; i++) {                                       \
            int g = tid + i*NTH;                                              \
            int row = g >> 2, seg = g & 3;                                    \
            *(uint4*)&sA[buf][row][seg*8] = ra[i];                            \
        }                                                                     \
        _Pragma("unroll")                                                     \
        for (int i = 0; i < NLB; i++) {                                       \
            int g = tid + i*NTH;                                              \
            int row = g >> 2, seg = g & 3;                                    \
            *(uint4*)&sB[buf][row][seg*8] = rb[i];                            \
        }                                                                     \
    }
#define H_COMP(buf)                                                           \
    {                                                                         \
        uint32_t aoff = (buf)*ABUF, boff = (buf)*BBUF;                        \
        _Pragma("unroll")                                                     \
        for (int ks = 0; ks < 2; ks++) {                                      \
            uint32_t af[4][4], bf[2][4];                                      \
            _Pragma("unroll")                                                 \
            for (int am = 0; am < 4; am++)                                    \
                ldsm4(af[am], a_addr[am] + aoff + ks*32);                     \
            _Pragma("unroll")                                                 \
            for (int p = 0; p < 2; p++)                                       \
                ldsm4(bf[p], b_addr[p] + boff + ks*32);                       \
            _Pragma("unroll")                                                 \
            for (int am = 0; am < 4; am++)                                    \
                _Pragma("unroll")                                             \
                for (int bn = 0; bn < 4; bn++)                                \
                    mma_bf16(c[am][bn], af[am], &bf[bn>>1][(bn&1)*2]);        \
        }                                                                     \
    }

    int nchunk = Keff >> 5;
    H_LDG(0);
    H_STS(0);
    __syncthreads();
    for (int ck = 0; ck < nchunk; ck++) {
        if (ck + 1 < nchunk) H_LDG((ck+1)*32);
        H_COMP(ck & 1);
        if (ck + 1 < nchunk) {
            H_STS((ck+1) & 1);
        }
        __syncthreads();
    }

    // epilogue: direct fp32 stores
#pragma unroll
    for (int am = 0; am < 4; am++) {
        int r0 = m0 + wm*64 + am*16 + (lane >> 2);
        int r1 = r0 + 8;
#pragma unroll
        for (int bn = 0; bn < 4; bn++) {
            int col = n0 + wn*32 + bn*8 + (lane & 3)*2;
            if (col < Nn) {
                if (r0 < M) *(float2*)(C + (long)r0*ldc + col) = make_float2(c[am][bn][0], c[am][bn][1]);
                if (r1 < M) *(float2*)(C + (long)r1*ldc + col) = make_float2(c[am][bn][2], c[am][bn][3]);
            }
        }
    }
#undef H_LDG
#undef H_STS
#undef H_COMP
}

// =========================================================================
// x_proj SGEMM (fp32): C[M,48(44 used)] = A[M,384] * B[44,384]^T
// =========================================================================
__global__ __launch_bounds__(256)
void sgemm_xp(const float* __restrict__ A, const float* __restrict__ Bm,
              float* __restrict__ C, int M)
{
    __shared__ float As[2][16][64];
    __shared__ float Bs[2][16][48];
    int tid = threadIdx.x;
    int m0 = blockIdx.x * 64;
    int tm = tid >> 4;          // 0..15 -> 4 rows each
    int tn = tid & 15;          // 0..15 -> 3 cols each
    int lrow = tid >> 2;        // 0..63
    int lkq  = tid & 3;         // 0..3

    float acc[4][3];
#pragma unroll
    for (int i = 0; i < 4; i++)
#pragma unroll
        for (int j = 0; j < 3; j++) acc[i][j] = 0.f;

    float4 ra, rb;
#define XLDG(k0)                                                              \
    {                                                                         \
        ra = (m0 + lrow < M)                                                  \
            ? *(const float4*)(A + (long)(m0+lrow)*DI_ + (k0) + lkq*4)        \
            : make_float4(0.f,0.f,0.f,0.f);                                   \
        rb = make_float4(0.f,0.f,0.f,0.f);                                    \
        if (tid < 192 && lrow < 44)                                           \
            rb = *(const float4*)(Bm + (long)lrow*DI_ + (k0) + lkq*4);        \
    }
#define XSTS(buf)                                                             \
    {                                                                         \
        As[buf][lkq*4+0][lrow] = ra.x; As[buf][lkq*4+1][lrow] = ra.y;         \
        As[buf][lkq*4+2][lrow] = ra.z; As[buf][lkq*4+3][lrow] = ra.w;         \
        if (tid < 192) {                                                      \
            Bs[buf][lkq*4+0][lrow] = rb.x; Bs[buf][lkq*4+1][lrow] = rb.y;     \
            Bs[buf][lkq*4+2][lrow] = rb.z; Bs[buf][lkq*4+3][lrow] = rb.w;     \
        }                                                                     \
    }
#define XCOMP(buf)                                                            \
    {                                                                         \
        _Pragma("unroll")                                                     \
        for (int kk = 0; kk < 16; kk++) {                                     \
            float a4[4];                                                      \
            *(float4*)a4 = *(const float4*)&As[buf][kk][tm*4];                \
            float b0 = Bs[buf][kk][tn*3+0];                                   \
            float b1 = Bs[buf][kk][tn*3+1];                                   \
            float b2 = Bs[buf][kk][tn*3+2];                                   \
            _Pragma("unroll")                                                 \
            for (int i = 0; i < 4; i++) {                                     \
                acc[i][0] = fmaf(a4[i], b0, acc[i][0]);                       \
                acc[i][1] = fmaf(a4[i], b1, acc[i][1]);                       \
                acc[i][2] = fmaf(a4[i], b2, acc[i][2]);                       \
            }                                                                 \
        }                                                                     \
    }

    XLDG(0); XSTS(0);
    __syncthreads();
    int buf = 0;
    for (int k0 = 16; k0 < DI_; k0 += 16) {
        XLDG(k0);
        XCOMP(buf);
        XSTS(buf ^ 1);
        __syncthreads();
        buf ^= 1;
    }
    XCOMP(buf);

#pragma unroll
    for (int i = 0; i < 4; i++) {
        int row = m0 + tm*4 + i;
        if (row < M) {
#pragma unroll
            for (int j = 0; j < 3; j++)
                C[(long)row*XP_ + tn*3 + j] = acc[i][j];
        }
    }
#undef XLDG
#undef XSTS
#undef XCOMP
}

// ---------------- causal depthwise conv(4) + silu, 4 channels/thread ----------------
__global__ void k_conv(const float* __restrict__ cw, const float* __restrict__ cb)
{
    int idx = blockIdx.x*blockDim.x + threadIdx.x;
    if (idx >= NTOK_*(DI_/4)) return;
    int c4 = idx % (DI_/4);
    int t  = idx / (DI_/4);
    int l  = t % L_;
    int d  = c4*4;

    float acc[4];
    *(float4*)acc = *(const float4*)(cb + d);
    float wv[4][4];          // wv[i][k] : channel d+i, tap k
#pragma unroll
    for (int i = 0; i < 4; i++)
        *(float4*)wv[i] = *(const float4*)(cw + (d+i)*4);
#pragma unroll
    for (int k = 0; k < 4; k++) {
        int ls = l - 3 + k;
        if (ls >= 0) {
            float x[4];
            *(float4*)x = *(const float4*)(g_xz + (long)(t-3+k)*(2*DI_) + d);
#pragma unroll
            for (int i = 0; i < 4; i++)
                acc[i] = fmaf(x[i], wv[i][k], acc[i]);
        }
    }
    float o[4];
#pragma unroll
    for (int i = 0; i < 4; i++)
        o[i] = acc[i] / (1.f + __expf(-acc[i]));
    *(float4*)(g_xc + (long)t*DI_ + d) = *(float4*)o;
}

// =========================================================================
// Fused selective scan with software-pipelined loads (exact R6 version).
// =========================================================================
__global__ __launch_bounds__(128)
void k_scan(const float* __restrict__ A_log, const float* __restrict__ Dsk,
            const float* __restrict__ dtw_g, const float* __restrict__ dtb_g)
{
    int local = blockIdx.x*128 + threadIdx.x;   // 0..1535
    int d = local >> 2;                          // 0..383
    int q = local & 3;                           // quarter of states
    int b = blockIdx.y;

    float a[4];
#pragma unroll
    for (int n = 0; n < 4; n++) a[n] = -__expf(A_log[d*NS_ + q*4 + n]);
    float w[NR_];
#pragma unroll
    for (int r = 0; r < NR_; r++) w[r] = dtw_g[d*NR_ + r];
    float dtb = dtb_g[d];
    float dsk = Dsk[d];
    float h[4] = {0.f, 0.f, 0.f, 0.f};

    long tbase = (long)b * L_;
    const float4* xr = (const float4*)(g_xdb + tbase*XP_);
    float4 r0 = xr[0], r1 = xr[1], r2 = xr[2];
    float4 Bq = xr[3+q], Cq = xr[7+q];
    float u = g_xc[tbase*DI_ + d];
    float z = g_xz[tbase*(2*DI_) + DI_ + d];

    for (int l = 0; l < L_; l++) {
        long t = tbase + l;
        long t2 = tbase + ((l+1 < L_) ? l+1 : l);
        const float4* x2 = (const float4*)(g_xdb + t2*XP_);
        float4 p0 = x2[0], p1 = x2[1], p2 = x2[2];
        float4 pB = x2[3+q], pC = x2[7+q];
        float pu = g_xc[t2*DI_ + d];
        float pz = g_xz[t2*(2*DI_) + DI_ + d];

        float a0 = dtb, a1 = 0.f;
        a0 = fmaf(r0.x, w[0], a0); a1 = fmaf(r0.y, w[1],  a1);
        a0 = fmaf(r0.z, w[2], a0); a1 = fmaf(r0.w, w[3],  a1);
        a0 = fmaf(r1.x, w[4], a0); a1 = fmaf(r1.y, w[5],  a1);
        a0 = fmaf(r1.z, w[6], a0); a1 = fmaf(r1.w, w[7],  a1);
        a0 = fmaf(r2.x, w[8], a0); a1 = fmaf(r2.y, w[9],  a1);
        a0 = fmaf(r2.z, w[10],a0); a1 = fmaf(r2.w, w[11], a1);
        float acc = a0 + a1;
        float dt = fmaxf(acc, 0.f) + __logf(1.f + __expf(-fabsf(acc)));
        float du = dt * u;

        float Bv[4] = {Bq.x, Bq.y, Bq.z, Bq.w};
        float Cv[4] = {Cq.x, Cq.y, Cq.z, Cq.w};
        float y = 0.f;
#pragma unroll
        for (int n = 0; n < 4; n++) {
            float dA = __expf(dt * a[n]);
            h[n] = fmaf(h[n], dA, du * Bv[n]);
            y = fmaf(h[n], Cv[n], y);
        }
        y += __shfl_xor_sync(0xffffffffu, y, 1);
        y += __shfl_xor_sync(0xffffffffu, y, 2);
        if (q == 0) {
            float sg = z / (1.f + __expf(-z));
            g_y[t*DI_ + d] = (y + u*dsk) * sg;
        }
        r0 = p0; r1 = p1; r2 = p2; Bq = pB; Cq = pC; u = pu; z = pz;
    }
}

// ---------------- layer-3 out_proj: only last tokens matter ----------------
__global__ void k_outlast(const float* __restrict__ ow)
{
    int b = blockIdx.x;
    int e = threadIdx.x;         // 192
    __shared__ float ys[DI_];
    int t = b*L_ + (L_-1);
    for (int i = e; i < DI_; i += E_) ys[i] = g_y[(long)t*DI_ + i];
    __syncthreads();
    float acc = 0.f;
    const float* w = ow + e*DI_;
#pragma unroll 4
    for (int d2 = 0; d2 < DI_; d2++) acc = fmaf(ys[d2], w[d2], acc);
    g_x[t*E_ + e] = acc;
}

// ---------------- final rmsnorm (last token) + classifier head ----------------
__global__ void k_final(const float* __restrict__ nfw, const float* __restrict__ hw,
                        const float* __restrict__ hb, float* __restrict__ out)
{
    int b = blockIdx.x;
    int e = threadIdx.x;         // 192
    int t = b*L_ + (L_-1);
    float r = g_x[t*E_ + e] + g_res[t*E_ + e];
    float s = r*r;
#pragma unroll
    for (int o = 16; o > 0; o >>= 1) s += __shfl_down_sync(0xffffffffu, s, o);
    __shared__ float ws[6];
    __shared__ float s_inv;
    __shared__ float vs[E_];
    int w = e >> 5, lane = e & 31;
    if (lane == 0) ws[w] = s;
    __syncthreads();
    if (e == 0) {
        float tot = ws[0]+ws[1]+ws[2]+ws[3]+ws[4]+ws[5];
        s_inv = rsqrtf(tot * (1.0f/E_) + EPS_);
    }
    __syncthreads();
    vs[e] = r * s_inv * nfw[e];
    __syncthreads();
    if (e < 20) {
        float acc = hb[e];
        const float* wr = hw + e*E_;
#pragma unroll 4
        for (int j = 0; j < E_; j++) acc = fmaf(vs[j], wr[j], acc);
        out[b*20 + e] = acc;
    }
}

// ---------------- launch ----------------
extern "C" void kernel_launch(void* const* d_in, const int* in_sizes, int n_in,
                              void* d_out, int out_size)
{
    const float* imgs      = (const float*)d_in[0];
    const float* patch_w   = (const float*)d_in[1];
    const float* patch_b   = (const float*)d_in[2];
    const float* cls_token = (const float*)d_in[3];
    const float* pos_embed = (const float*)d_in[4];
    const float* cnn_w     = (const float*)d_in[5];
    const float* cnn_b     = (const float*)d_in[6];
    const float* norm_w    = (const float*)d_in[7];
    const float* in_proj_w = (const float*)d_in[8];
    const float* conv_w    = (const float*)d_in[9];
    const float* conv_b    = (const float*)d_in[10];
    const float* x_proj_w  = (const float*)d_in[11];
    const float* dt_proj_w = (const float*)d_in[12];
    const float* dt_proj_b = (const float*)d_in[13];
    const float* A_log     = (const float*)d_in[14];
    const float* D_skip    = (const float*)d_in[15];
    const float* out_proj_w= (const float*)d_in[16];
    const float* norm_f_w  = (const float*)d_in[17];
    const float* head_w    = (const float*)d_in[18];
    const float* head_b    = (const float*)d_in[19];
    float* out = (float*)d_out;

    float *p_xz, *p_xdb, *p_y, *p_x, *p_xc;
    __nv_bfloat16 *p_a2, *p_a2o, *p_b2, *p_b2o;
    cudaGetSymbolAddress((void**)&p_xz,  g_xz);
    cudaGetSymbolAddress((void**)&p_xdb, g_xdb);
    cudaGetSymbolAddress((void**)&p_y,   g_y);
    cudaGetSymbolAddress((void**)&p_x,   g_x);
    cudaGetSymbolAddress((void**)&p_xc,  g_xc);
    cudaGetSymbolAddress((void**)&p_a2,  g_a2);
    cudaGetSymbolAddress((void**)&p_a2o, g_a2o);
    cudaGetSymbolAddress((void**)&p_b2,  g_b2);
    cudaGetSymbolAddress((void**)&p_b2o, g_b2o);

    // 1-2: batched vectorized weight splits (all layers at once)
    k_wcvt<<<dim3((768*E_/4+255)/256, 4), 256>>>(in_proj_w, p_b2, 768, E_,
                                                 (long)768*E_, (long)768*3*E_);
    k_wcvt<<<dim3((E_*DI_/4+255)/256, 3), 256>>>(out_proj_w, p_b2o, E_, DI_,
                                                 (long)E_*DI_, (long)E_*3*DI_);
    // 3: embed + layer-0 rmsnorm + A-split fused
    k_embed_norm<<<NTOK_, 192>>>(imgs, patch_w, patch_b, cls_token,
                                 pos_embed, cnn_w, cnn_b, norm_w);

    const int MGRID = (NTOK_ + 127) / 128;   // 101
    dim3 gIn (6, MGRID);    // N tiles of 128 over 768
    dim3 gOut(3, MGRID);    // N tiles of 64 over 192
    int ew_blocks  = (NTOK_*(DI_/4) + 255)/256;
    int xp_blocks  = (NTOK_ + 63) / 64;      // 201
    int acvt_out_b = (NTOK_*(DI_/4) + 255)/256;

    for (int i = 0; i < 4; i++) {
        if (i > 0)
            k_resnorm<<<NTOK_/2, 384>>>(norm_w + i*E_);
        // launch 4 of the whole sequence = this hgemm2 (layer 0) -> ncu target
        hgemm2<<<gIn, 128>>>(p_a2, p_b2 + (long)i*768*3*E_, p_xz,
                             NTOK_, 3*E_, 2*DI_);
        k_conv<<<ew_blocks, 256>>>(conv_w + (long)i*DI_*4, conv_b + i*DI_);
        sgemm_xp<<<xp_blocks, 256>>>(p_xc, x_proj_w + (long)i*(NR_+2*NS_)*DI_,
                                     p_xdb, NTOK_);
        k_scan<<<dim3(12, BATCH_), 128>>>(A_log + (long)i*DI_*NS_, D_skip + i*DI_,
                                          dt_proj_w + (long)i*DI_*NR_,
                                          dt_proj_b + i*DI_);
        if (i < 3) {
            k_acvt<<<acvt_out_b, 256>>>(p_y, p_a2o, NTOK_, DI_);
            hgemm<64,128><<<gOut, 128>>>(p_a2o, p_b2o + (long)i*E_*3*DI_, p_x,
                                         NTOK_, 3*DI_, E_, E_);
        } else {
            k_outlast<<<BATCH_, E_>>>(out_proj_w + (long)i*E_*DI_);
        }
    }
    k_final<<<BATCH_, E_>>>(norm_f_w, head_w, head_b, out);
}